// round 3
// baseline (speedup 1.0000x reference)
#include <cuda_runtime.h>
#include <math.h>

#define DHID 128
#define MAX_ENTS 100000
#define MAX_RELS 1000
#define RRELU_SLOPE 0.22916666666666666f

__device__ float g_hW[MAX_ENTS * DHID];
__device__ float g_relW[MAX_RELS * DHID];

typedef unsigned long long ull;

__device__ __forceinline__ void ffma2(ull& d, ull a, ull b) {
    asm("fma.rn.f32x2 %0, %1, %2, %3;" : "=l"(d) : "l"(a), "l"(b), "l"(d));
}
__device__ __forceinline__ float pairsum(ull v) {
    float x, y;
    asm("mov.b64 {%0,%1}, %2;" : "=f"(x), "=f"(y) : "l"(v));
    return x + y;
}
__device__ __forceinline__ ull pack2(float x, float y) {
    ull r; asm("mov.b64 %0, {%1, %2};" : "=l"(r) : "f"(x), "f"(y)); return r;
}
__device__ __forceinline__ void unpack2(ull v, float& x, float& y) {
    asm("mov.b64 {%0, %1}, %2;" : "=f"(x), "=f"(y) : "l"(v));
}

// ---------------------------------------------------------------------------
// Kernel A: persistent. Normalize 64 rows/tile; dual GEMM h@Wn -> hW,
// h@Ws -> agg (d_out). 512 threads = 16 warps; warps 0-7 -> Wn, 8-15 -> Ws,
// each warp 8 rows. W packed k-pairwise in smem once per block:
// Wp[p][c] = (W[2p][c], W[2p+1][c]) as 64-bit, c in [0,256).
// ---------------------------------------------------------------------------
extern "C" __global__ void __launch_bounds__(512)
k_norm_dual_gemm(const float* __restrict__ ent,
                 const float* __restrict__ Wn,
                 const float* __restrict__ Ws,
                 float* __restrict__ hW,
                 float* __restrict__ agg,
                 int N, int numTiles)
{
    extern __shared__ float sm[];
    float* Wf = sm;                 // 128*256 floats, packed layout
    float* hs = sm + 128 * 256;     // 64*128
    const ull* Wp = (const ull*)Wf;
    const int tid  = threadIdx.x;
    const int lane = tid & 31;
    const int w    = tid >> 5;      // 0..15

    // Pack weights once per block: (k,c) -> Wf[(k>>1)*512 + c*2 + (k&1)]
    for (int t = tid; t < (128 * 256) / 4; t += 512) {
        int word = t * 4;
        int k = word >> 8;
        int c = word & 255;
        float4 v = (c < 128) ? *(const float4*)(Wn + k * 128 + c)
                             : *(const float4*)(Ws + k * 128 + (c - 128));
        int pb = (k >> 1) * 512 + (k & 1);
        Wf[pb + (c + 0) * 2] = v.x;
        Wf[pb + (c + 1) * 2] = v.y;
        Wf[pb + (c + 2) * 2] = v.z;
        Wf[pb + (c + 3) * 2] = v.w;
    }
    __syncthreads();

    const int mat   = w >> 3;             // 0 -> hW, 1 -> agg
    const int r0    = (w & 7) * 8;
    const int cbase = mat * 128 + lane * 4;
    float* outp = mat ? agg : hW;

    for (int tile = blockIdx.x; tile < numTiles; tile += gridDim.x) {
        const int base = tile * 64;

        // normalize: warp w handles rows 4w..4w+3
        #pragma unroll
        for (int rr = 0; rr < 4; rr++) {
            int row  = w * 4 + rr;
            int node = base + row;
            float4 v = make_float4(0.f, 0.f, 0.f, 0.f);
            if (node < N) v = *(const float4*)(ent + (size_t)node * 128 + lane * 4);
            float ss = v.x * v.x + v.y * v.y + v.z * v.z + v.w * v.w;
            #pragma unroll
            for (int off = 16; off > 0; off >>= 1)
                ss += __shfl_xor_sync(0xffffffffu, ss, off);
            float rn = 1.0f / fmaxf(sqrtf(ss), 1e-12f);
            *(float4*)(hs + row * 128 + lane * 4) =
                make_float4(v.x * rn, v.y * rn, v.z * rn, v.w * rn);
        }
        __syncthreads();

        ull acc[8][4];
        #pragma unroll
        for (int j = 0; j < 8; j++)
            #pragma unroll
            for (int i = 0; i < 4; i++) acc[j][i] = 0ull;

        #pragma unroll 2
        for (int kk = 0; kk < 128; kk += 4) {
            int p = kk >> 1;
            ulonglong2 b00 = *(const ulonglong2*)(Wp + p * 256 + cbase);
            ulonglong2 b01 = *(const ulonglong2*)(Wp + p * 256 + cbase + 2);
            ulonglong2 b10 = *(const ulonglong2*)(Wp + (p + 1) * 256 + cbase);
            ulonglong2 b11 = *(const ulonglong2*)(Wp + (p + 1) * 256 + cbase + 2);
            #pragma unroll
            for (int j = 0; j < 8; j++) {
                ulonglong2 a01 = *(const ulonglong2*)(hs + (r0 + j) * 128 + kk);
                ffma2(acc[j][0], a01.x, b00.x);
                ffma2(acc[j][1], a01.x, b00.y);
                ffma2(acc[j][2], a01.x, b01.x);
                ffma2(acc[j][3], a01.x, b01.y);
                ffma2(acc[j][0], a01.y, b10.x);
                ffma2(acc[j][1], a01.y, b10.y);
                ffma2(acc[j][2], a01.y, b11.x);
                ffma2(acc[j][3], a01.y, b11.y);
            }
        }

        #pragma unroll
        for (int j = 0; j < 8; j++) {
            int node = base + r0 + j;
            if (node < N) {
                float4 o = make_float4(pairsum(acc[j][0]), pairsum(acc[j][1]),
                                       pairsum(acc[j][2]), pairsum(acc[j][3]));
                *(float4*)(outp + (size_t)node * 128 + lane * 4) = o;
            }
        }
        __syncthreads();
    }
}

// ---------------------------------------------------------------------------
// Kernel B: relW = rel_emb @ W_neighbor (tiny) — unchanged style
// ---------------------------------------------------------------------------
extern "C" __global__ void __launch_bounds__(512)
k_rel_gemm(const float* __restrict__ rel,
           const float* __restrict__ Wn,
           float* __restrict__ relW,
           int R)
{
    extern __shared__ float sm[];
    float* Wsh = sm;             // 128*128
    float* hs  = sm + 128 * 128; // 64*128
    const int tid  = threadIdx.x;
    const int base = blockIdx.x * 64;
    const int lane = tid & 31;
    const int w    = tid >> 5;

    for (int t = tid; t < (128 * 128) / 4; t += 512)
        *(float4*)(Wsh + t * 4) = *(const float4*)(Wn + t * 4);

    #pragma unroll
    for (int rr = 0; rr < 4; rr++) {
        int row = w * 4 + rr;
        int r   = base + row;
        float4 v = make_float4(0.f, 0.f, 0.f, 0.f);
        if (r < R) v = *(const float4*)(rel + (size_t)r * 128 + lane * 4);
        *(float4*)(hs + row * 128 + lane * 4) = v;
    }
    __syncthreads();

    const int r0 = w * 4;
    ull acc[4][2];
    #pragma unroll
    for (int j = 0; j < 4; j++) acc[j][0] = acc[j][1] = 0ull;

    #pragma unroll 2
    for (int kk = 0; kk < 128; kk += 4) {
        float a[4][4];
        #pragma unroll
        for (int j = 0; j < 4; j++) {
            float4 v = *(const float4*)(hs + (r0 + j) * 128 + kk);
            a[j][0] = v.x; a[j][1] = v.y; a[j][2] = v.z; a[j][3] = v.w;
        }
        #pragma unroll
        for (int t = 0; t < 4; t++) {
            float4 b = *(const float4*)(Wsh + (kk + t) * 128 + lane * 4);
            ull b0 = pack2(b.x, b.y), b1 = pack2(b.z, b.w);
            #pragma unroll
            for (int j = 0; j < 4; j++) {
                ull ap = pack2(a[j][t], a[j][t]);
                ffma2(acc[j][0], ap, b0);
                ffma2(acc[j][1], ap, b1);
            }
        }
    }

    #pragma unroll
    for (int j = 0; j < 4; j++) {
        int r = base + r0 + j;
        if (r >= R) continue;
        float4 o;
        unpack2(acc[j][0], o.x, o.y); unpack2(acc[j][1], o.z, o.w);
        *(float4*)(relW + (size_t)r * 128 + lane * 4) = o;
    }
}

// ---------------------------------------------------------------------------
// Kernel C: edge scatter (L2-bound)
// ---------------------------------------------------------------------------
extern "C" __global__ void __launch_bounds__(256)
k_edge(const float* __restrict__ hW,
       const float* __restrict__ relW,
       const float* __restrict__ enorm,
       const int* __restrict__ src,
       const int* __restrict__ dst,
       const int* __restrict__ et,
       float* __restrict__ agg,
       int E)
{
    int e = blockIdx.x * 8 + (threadIdx.x >> 5);
    if (e >= E) return;
    int lane = threadIdx.x & 31;

    int   s = __ldg(src + e);
    int   d = __ldg(dst + e);
    int   t = __ldg(et + e);
    float n = __ldg(enorm + e);

    int c = lane * 4;
    float4 a = *(const float4*)(hW   + (size_t)s * 128 + c);
    float4 b = *(const float4*)(relW + (size_t)t * 128 + c);
    float4 v = make_float4((a.x + b.x) * n, (a.y + b.y) * n,
                           (a.z + b.z) * n, (a.w + b.w) * n);
    float* p = agg + (size_t)d * 128 + c;
    asm volatile("red.global.add.v4.f32 [%0], {%1,%2,%3,%4};"
                 :: "l"(p), "f"(v.x), "f"(v.y), "f"(v.z), "f"(v.w)
                 : "memory");
}

// ---------------------------------------------------------------------------
// Kernel D: persistent. h_cur = rrelu(agg); gate = sigmoid(h_cur@Wt + b);
// out = gate*h_cur + (1-gate)*his. 256 threads = 8 warps x 8 rows.
// ---------------------------------------------------------------------------
extern "C" __global__ void __launch_bounds__(256, 2)
k_final(float* __restrict__ x,
        const float* __restrict__ Wt,
        const float* __restrict__ bias,
        const float* __restrict__ his,
        int N, int numTiles)
{
    extern __shared__ float sm[];
    float* Wf = sm;              // 128*128 packed
    float* hs = sm + 128 * 128;  // 64*128 post-rrelu
    const ull* Wp = (const ull*)Wf;
    const int tid  = threadIdx.x;
    const int lane = tid & 31;
    const int w    = tid >> 5;   // 0..7

    // Pack Wt once per block: (k,c) -> Wf[(k>>1)*256 + c*2 + (k&1)]
    for (int t = tid; t < (128 * 128) / 4; t += 256) {
        int word = t * 4;
        int k = word >> 7;
        int c = word & 127;
        float4 v = *(const float4*)(Wt + k * 128 + c);
        int pb = (k >> 1) * 256 + (k & 1);
        Wf[pb + (c + 0) * 2] = v.x;
        Wf[pb + (c + 1) * 2] = v.y;
        Wf[pb + (c + 2) * 2] = v.z;
        Wf[pb + (c + 3) * 2] = v.w;
    }
    __syncthreads();

    const int r0    = w * 8;
    const int cbase = lane * 4;
    float4 bv = *(const float4*)(bias + cbase);

    for (int tile = blockIdx.x; tile < numTiles; tile += gridDim.x) {
        const int base = tile * 64;

        // load + rrelu: warp w handles rows 8w..8w+7
        #pragma unroll
        for (int rr = 0; rr < 8; rr++) {
            int row  = w * 8 + rr;
            int node = base + row;
            float4 v = make_float4(0.f, 0.f, 0.f, 0.f);
            if (node < N) v = *(const float4*)(x + (size_t)node * 128 + lane * 4);
            v.x = v.x >= 0.f ? v.x : RRELU_SLOPE * v.x;
            v.y = v.y >= 0.f ? v.y : RRELU_SLOPE * v.y;
            v.z = v.z >= 0.f ? v.z : RRELU_SLOPE * v.z;
            v.w = v.w >= 0.f ? v.w : RRELU_SLOPE * v.w;
            *(float4*)(hs + row * 128 + lane * 4) = v;
        }
        __syncthreads();

        ull acc[8][4];
        #pragma unroll
        for (int j = 0; j < 8; j++)
            #pragma unroll
            for (int i = 0; i < 4; i++) acc[j][i] = 0ull;

        #pragma unroll 2
        for (int kk = 0; kk < 128; kk += 4) {
            int p = kk >> 1;
            ulonglong2 b00 = *(const ulonglong2*)(Wp + p * 128 + cbase);
            ulonglong2 b01 = *(const ulonglong2*)(Wp + p * 128 + cbase + 2);
            ulonglong2 b10 = *(const ulonglong2*)(Wp + (p + 1) * 128 + cbase);
            ulonglong2 b11 = *(const ulonglong2*)(Wp + (p + 1) * 128 + cbase + 2);
            #pragma unroll
            for (int j = 0; j < 8; j++) {
                ulonglong2 a01 = *(const ulonglong2*)(hs + (r0 + j) * 128 + kk);
                ffma2(acc[j][0], a01.x, b00.x);
                ffma2(acc[j][1], a01.x, b00.y);
                ffma2(acc[j][2], a01.x, b01.x);
                ffma2(acc[j][3], a01.x, b01.y);
                ffma2(acc[j][0], a01.y, b10.x);
                ffma2(acc[j][1], a01.y, b10.y);
                ffma2(acc[j][2], a01.y, b11.x);
                ffma2(acc[j][3], a01.y, b11.y);
            }
        }

        #pragma unroll
        for (int j = 0; j < 8; j++) {
            int node = base + r0 + j;
            if (node < N) {
                float g0 = pairsum(acc[j][0]) + bv.x;
                float g1 = pairsum(acc[j][1]) + bv.y;
                float g2 = pairsum(acc[j][2]) + bv.z;
                float g3 = pairsum(acc[j][3]) + bv.w;
                float s0 = 1.0f / (1.0f + __expf(-g0));
                float s1 = 1.0f / (1.0f + __expf(-g1));
                float s2 = 1.0f / (1.0f + __expf(-g2));
                float s3 = 1.0f / (1.0f + __expf(-g3));
                float4 hv = *(const float4*)(hs + (r0 + j) * 128 + cbase);
                float4 hh = *(const float4*)(his + (size_t)node * 128 + cbase);
                float4 o = make_float4(s0 * hv.x + (1.f - s0) * hh.x,
                                       s1 * hv.y + (1.f - s1) * hh.y,
                                       s2 * hv.z + (1.f - s2) * hh.z,
                                       s3 * hv.w + (1.f - s3) * hh.w);
                *(float4*)(x + (size_t)node * 128 + cbase) = o;
            }
        }
        __syncthreads();
    }
}

// ---------------------------------------------------------------------------
extern "C" void kernel_launch(void* const* d_in, const int* in_sizes, int n_in,
                              void* d_out, int out_size)
{
    const float* ent   = (const float*)d_in[0];
    const float* rel   = (const float*)d_in[1];
    const float* his   = (const float*)d_in[2];
    const float* Wn    = (const float*)d_in[3];
    const float* Ws    = (const float*)d_in[4];
    const float* Wt    = (const float*)d_in[5];
    const float* bias  = (const float*)d_in[6];
    const float* enorm = (const float*)d_in[7];
    const int*   src   = (const int*)d_in[8];
    const int*   dst   = (const int*)d_in[9];
    const int*   et    = (const int*)d_in[10];

    int N = in_sizes[0] / DHID;
    int R = in_sizes[1] / DHID;
    int E = in_sizes[7];
    float* out = (float*)d_out;

    float *hW, *relW;
    cudaGetSymbolAddress((void**)&hW, g_hW);
    cudaGetSymbolAddress((void**)&relW, g_relW);

    int dev = 0, sms = 148;
    cudaGetDevice(&dev);
    cudaDeviceGetAttribute(&sms, cudaDevAttrMultiProcessorCount, dev);

    const int numTiles = (N + 63) / 64;
    const int smA = (128 * 256 + 64 * 128) * sizeof(float); // 160 KB
    const int smB = (128 * 128 + 64 * 128) * sizeof(float); //  96 KB
    cudaFuncSetAttribute(k_norm_dual_gemm, cudaFuncAttributeMaxDynamicSharedMemorySize, smA);
    cudaFuncSetAttribute(k_rel_gemm,       cudaFuncAttributeMaxDynamicSharedMemorySize, smB);
    cudaFuncSetAttribute(k_final,          cudaFuncAttributeMaxDynamicSharedMemorySize, smB);

    k_norm_dual_gemm<<<sms, 512, smA>>>(ent, Wn, Ws, hW, out, N, numTiles);
    k_rel_gemm<<<(R + 63) / 64, 512, smB>>>(rel, Wn, relW, R);
    k_edge<<<(E + 7) / 8, 256>>>(hW, relW, enorm, src, dst, et, out, E);
    k_final<<<2 * sms, 256, smB>>>(out, Wt, bias, his, N, numTiles);
}

// round 5
// speedup vs baseline: 1.3239x; 1.3239x over previous
#include <cuda_runtime.h>
#include <cstdint>
#include <math.h>

#define DHID 128
#define MAX_ENTS 100000
#define MAX_RELS 1000
#define RRELU_SLOPE 0.22916666666666666f
#define PAD 132

__device__ float g_hW[MAX_ENTS * DHID];
__device__ float g_relW[MAX_RELS * DHID];

typedef unsigned long long ull;
typedef uint32_t u32;

__device__ __forceinline__ u32 f2tf(float x) {
    u32 r; asm("cvt.rna.tf32.f32 %0, %1;" : "=r"(r) : "f"(x)); return r;
}
__device__ __forceinline__ void mma8(float* c, u32 a0, u32 a1, u32 a2, u32 a3,
                                     u32 b0, u32 b1) {
    asm volatile(
        "mma.sync.aligned.m16n8k8.row.col.f32.tf32.tf32.f32 "
        "{%0,%1,%2,%3}, {%4,%5,%6,%7}, {%8,%9}, {%0,%1,%2,%3};"
        : "+f"(c[0]), "+f"(c[1]), "+f"(c[2]), "+f"(c[3])
        : "r"(a0), "r"(a1), "r"(a2), "r"(a3), "r"(b0), "r"(b1));
}

// ---------------------------------------------------------------------------
// Kernel A: persistent. Per 128-row tile: L2-normalize ent -> tf32 A in smem;
// dual tf32 mma.sync GEMM vs WnT and WsT -> hW, agg(d_out).
// 512 thr = 16 warps; warp (wr=w>>2, wc=w&3) covers rows 32wr..+32, cols 32wc..+32.
// smem: WTn[128][132] | WTs[128][132] | hs[128][132] (tf32 bits)
// ---------------------------------------------------------------------------
extern "C" __global__ void __launch_bounds__(512, 1)
k_tensor_dual(const float* __restrict__ ent,
              const float* __restrict__ Wn,
              const float* __restrict__ Ws,
              float* __restrict__ hW,
              float* __restrict__ agg,
              int N, int numTiles)
{
    extern __shared__ float sm[];
    u32* WTn = (u32*)sm;                    // [n][k] tf32
    u32* WTs = WTn + 128 * PAD;
    u32* hs  = WTs + 128 * PAD;             // [row][k] tf32
    const int tid  = threadIdx.x;
    const int lane = tid & 31;
    const int w    = tid >> 5;
    const int gid  = lane >> 2;
    const int t4   = lane & 3;

    for (int idx = tid; idx < 128 * 128; idx += 512) {
        int k = idx >> 7, n = idx & 127;
        WTn[n * PAD + k] = f2tf(Wn[idx]);
        WTs[n * PAD + k] = f2tf(Ws[idx]);
    }
    __syncthreads();

    const int rb = (w >> 2) * 32;
    const int cb = (w & 3) * 32;

    for (int tile = blockIdx.x; tile < numTiles; tile += gridDim.x) {
        const int base = tile * 128;

        // normalize 8 rows per warp -> tf32 smem
        #pragma unroll
        for (int rr = 0; rr < 8; rr++) {
            int row = w * 8 + rr, node = base + row;
            float4 v = make_float4(0.f, 0.f, 0.f, 0.f);
            if (node < N) v = *(const float4*)(ent + (size_t)node * 128 + lane * 4);
            float ss = v.x * v.x + v.y * v.y + v.z * v.z + v.w * v.w;
            #pragma unroll
            for (int off = 16; off > 0; off >>= 1)
                ss += __shfl_xor_sync(0xffffffffu, ss, off);
            float rn = 1.0f / fmaxf(sqrtf(ss), 1e-12f);
            uint4 o = make_uint4(f2tf(v.x * rn), f2tf(v.y * rn),
                                 f2tf(v.z * rn), f2tf(v.w * rn));
            *(uint4*)(hs + row * PAD + lane * 4) = o;
        }
        __syncthreads();

        float aN[2][4][4], aS[2][4][4];
        #pragma unroll
        for (int mt = 0; mt < 2; mt++)
            #pragma unroll
            for (int nt = 0; nt < 4; nt++)
                #pragma unroll
                for (int i = 0; i < 4; i++) { aN[mt][nt][i] = 0.f; aS[mt][nt][i] = 0.f; }

        #pragma unroll
        for (int s = 0; s < 16; s++) {
            const int kb = s * 8;
            u32 A[2][4];
            #pragma unroll
            for (int mt = 0; mt < 2; mt++) {
                int r0 = rb + mt * 16 + gid;
                A[mt][0] = hs[r0 * PAD + kb + t4];
                A[mt][1] = hs[(r0 + 8) * PAD + kb + t4];
                A[mt][2] = hs[r0 * PAD + kb + t4 + 4];
                A[mt][3] = hs[(r0 + 8) * PAD + kb + t4 + 4];
            }
            #pragma unroll
            for (int nt = 0; nt < 4; nt++) {
                int c0 = cb + nt * 8 + gid;
                u32 bn0 = WTn[c0 * PAD + kb + t4];
                u32 bn1 = WTn[c0 * PAD + kb + t4 + 4];
                u32 bs0 = WTs[c0 * PAD + kb + t4];
                u32 bs1 = WTs[c0 * PAD + kb + t4 + 4];
                mma8(aN[0][nt], A[0][0], A[0][1], A[0][2], A[0][3], bn0, bn1);
                mma8(aN[1][nt], A[1][0], A[1][1], A[1][2], A[1][3], bn0, bn1);
                mma8(aS[0][nt], A[0][0], A[0][1], A[0][2], A[0][3], bs0, bs1);
                mma8(aS[1][nt], A[1][0], A[1][1], A[1][2], A[1][3], bs0, bs1);
            }
        }

        #pragma unroll
        for (int mt = 0; mt < 2; mt++)
            #pragma unroll
            for (int nt = 0; nt < 4; nt++) {
                int rl = rb + mt * 16 + gid;
                int c  = cb + nt * 8 + 2 * t4;
                int n0 = base + rl, n1 = base + rl + 8;
                if (n0 < N) {
                    *(float2*)(hW  + (size_t)n0 * 128 + c) =
                        make_float2(aN[mt][nt][0], aN[mt][nt][1]);
                    *(float2*)(agg + (size_t)n0 * 128 + c) =
                        make_float2(aS[mt][nt][0], aS[mt][nt][1]);
                }
                if (n1 < N) {
                    *(float2*)(hW  + (size_t)n1 * 128 + c) =
                        make_float2(aN[mt][nt][2], aN[mt][nt][3]);
                    *(float2*)(agg + (size_t)n1 * 128 + c) =
                        make_float2(aS[mt][nt][2], aS[mt][nt][3]);
                }
            }
        __syncthreads();
    }
}

// ---------------------------------------------------------------------------
// Kernel D: persistent. h_cur = rrelu(agg); gate = sigmoid(h_cur@Wt + b);
// out = gate*h_cur + (1-gate)*his. tf32 mma.sync; hs holds fp32 h_cur.
// smem: WTt[128][132] (tf32) | hs[128][132] (fp32)
// ---------------------------------------------------------------------------
extern "C" __global__ void __launch_bounds__(512, 1)
k_tensor_final(float* __restrict__ x,
               const float* __restrict__ Wt,
               const float* __restrict__ bias,
               const float* __restrict__ his,
               int N, int numTiles)
{
    extern __shared__ float sm[];
    u32*   WTt = (u32*)sm;            // [n][k] tf32
    float* hs  = sm + 128 * PAD;      // [row][k] fp32
    const int tid  = threadIdx.x;
    const int lane = tid & 31;
    const int w    = tid >> 5;
    const int gid  = lane >> 2;
    const int t4   = lane & 3;

    for (int idx = tid; idx < 128 * 128; idx += 512) {
        int k = idx >> 7, n = idx & 127;
        WTt[n * PAD + k] = f2tf(Wt[idx]);
    }
    __syncthreads();

    const int rb = (w >> 2) * 32;
    const int cb = (w & 3) * 32;

    for (int tile = blockIdx.x; tile < numTiles; tile += gridDim.x) {
        const int base = tile * 128;

        #pragma unroll
        for (int rr = 0; rr < 8; rr++) {
            int row = w * 8 + rr, node = base + row;
            float4 v = make_float4(0.f, 0.f, 0.f, 0.f);
            if (node < N) v = *(const float4*)(x + (size_t)node * 128 + lane * 4);
            v.x = v.x >= 0.f ? v.x : RRELU_SLOPE * v.x;
            v.y = v.y >= 0.f ? v.y : RRELU_SLOPE * v.y;
            v.z = v.z >= 0.f ? v.z : RRELU_SLOPE * v.z;
            v.w = v.w >= 0.f ? v.w : RRELU_SLOPE * v.w;
            *(float4*)(hs + row * PAD + lane * 4) = v;
        }
        __syncthreads();

        float acc[2][4][4];
        #pragma unroll
        for (int mt = 0; mt < 2; mt++)
            #pragma unroll
            for (int nt = 0; nt < 4; nt++)
                #pragma unroll
                for (int i = 0; i < 4; i++) acc[mt][nt][i] = 0.f;

        #pragma unroll
        for (int s = 0; s < 16; s++) {
            const int kb = s * 8;
            u32 A[2][4];
            #pragma unroll
            for (int mt = 0; mt < 2; mt++) {
                int r0 = rb + mt * 16 + gid;
                A[mt][0] = f2tf(hs[r0 * PAD + kb + t4]);
                A[mt][1] = f2tf(hs[(r0 + 8) * PAD + kb + t4]);
                A[mt][2] = f2tf(hs[r0 * PAD + kb + t4 + 4]);
                A[mt][3] = f2tf(hs[(r0 + 8) * PAD + kb + t4 + 4]);
            }
            #pragma unroll
            for (int nt = 0; nt < 4; nt++) {
                int c0 = cb + nt * 8 + gid;
                u32 b0 = WTt[c0 * PAD + kb + t4];
                u32 b1 = WTt[c0 * PAD + kb + t4 + 4];
                mma8(acc[0][nt], A[0][0], A[0][1], A[0][2], A[0][3], b0, b1);
                mma8(acc[1][nt], A[1][0], A[1][1], A[1][2], A[1][3], b0, b1);
            }
        }

        #pragma unroll
        for (int mt = 0; mt < 2; mt++)
            #pragma unroll
            for (int nt = 0; nt < 4; nt++) {
                int rl = rb + mt * 16 + gid;
                int c  = cb + nt * 8 + 2 * t4;
                float2 bv = *(const float2*)(bias + c);
                int nodes[2] = { base + rl, base + rl + 8 };
                #pragma unroll
                for (int half = 0; half < 2; half++) {
                    int node = nodes[half];
                    if (node >= N) continue;
                    int row = rl + half * 8;
                    float l0 = acc[mt][nt][half * 2 + 0] + bv.x;
                    float l1 = acc[mt][nt][half * 2 + 1] + bv.y;
                    float s0 = 1.0f / (1.0f + __expf(-l0));
                    float s1 = 1.0f / (1.0f + __expf(-l1));
                    float2 hv = *(const float2*)(hs + row * PAD + c);
                    float2 hh = *(const float2*)(his + (size_t)node * 128 + c);
                    float2 o = make_float2(s0 * hv.x + (1.f - s0) * hh.x,
                                           s1 * hv.y + (1.f - s1) * hh.y);
                    *(float2*)(x + (size_t)node * 128 + c) = o;
                }
            }
        __syncthreads();
    }
}

// ---------------------------------------------------------------------------
// Kernel B: relW = rel_emb @ W_neighbor (tiny, SIMT f32x2)
// ---------------------------------------------------------------------------
__device__ __forceinline__ void ffma2(ull& d, ull a, ull b) {
    asm("fma.rn.f32x2 %0, %1, %2, %3;" : "=l"(d) : "l"(a), "l"(b), "l"(d));
}
__device__ __forceinline__ ull pack2(float x, float y) {
    ull r; asm("mov.b64 %0, {%1, %2};" : "=l"(r) : "f"(x), "f"(y)); return r;
}
__device__ __forceinline__ void unpack2(ull v, float& x, float& y) {
    asm("mov.b64 {%0, %1}, %2;" : "=f"(x), "=f"(y) : "l"(v));
}

extern "C" __global__ void __launch_bounds__(512)
k_rel_gemm(const float* __restrict__ rel,
           const float* __restrict__ Wn,
           float* __restrict__ relW,
           int R)
{
    extern __shared__ float sm[];
    float* Wsh = sm;
    float* hsr = sm + 128 * 128;
    const int tid  = threadIdx.x;
    const int base = blockIdx.x * 64;
    const int lane = tid & 31;
    const int w    = tid >> 5;

    for (int t = tid; t < (128 * 128) / 4; t += 512)
        *(float4*)(Wsh + t * 4) = *(const float4*)(Wn + t * 4);

    #pragma unroll
    for (int rr = 0; rr < 4; rr++) {
        int row = w * 4 + rr;
        int r   = base + row;
        float4 v = make_float4(0.f, 0.f, 0.f, 0.f);
        if (r < R) v = *(const float4*)(rel + (size_t)r * 128 + lane * 4);
        *(float4*)(hsr + row * 128 + lane * 4) = v;
    }
    __syncthreads();

    const int r0 = w * 4;
    ull acc[4][2];
    #pragma unroll
    for (int j = 0; j < 4; j++) acc[j][0] = acc[j][1] = 0ull;

    #pragma unroll 2
    for (int kk = 0; kk < 128; kk += 4) {
        float a[4][4];
        #pragma unroll
        for (int j = 0; j < 4; j++) {
            float4 v = *(const float4*)(hsr + (r0 + j) * 128 + kk);
            a[j][0] = v.x; a[j][1] = v.y; a[j][2] = v.z; a[j][3] = v.w;
        }
        #pragma unroll
        for (int t = 0; t < 4; t++) {
            float4 b = *(const float4*)(Wsh + (kk + t) * 128 + lane * 4);
            ull b0 = pack2(b.x, b.y), b1 = pack2(b.z, b.w);
            #pragma unroll
            for (int j = 0; j < 4; j++) {
                ull ap = pack2(a[j][t], a[j][t]);
                ffma2(acc[j][0], ap, b0);
                ffma2(acc[j][1], ap, b1);
            }
        }
    }

    #pragma unroll
    for (int j = 0; j < 4; j++) {
        int r = base + r0 + j;
        if (r >= R) continue;
        float4 o;
        unpack2(acc[j][0], o.x, o.y); unpack2(acc[j][1], o.z, o.w);
        *(float4*)(relW + (size_t)r * 128 + lane * 4) = o;
    }
}

// ---------------------------------------------------------------------------
// Kernel C: edge scatter (L2-bound)
// ---------------------------------------------------------------------------
extern "C" __global__ void __launch_bounds__(256)
k_edge(const float* __restrict__ hW,
       const float* __restrict__ relW,
       const float* __restrict__ enorm,
       const int* __restrict__ src,
       const int* __restrict__ dst,
       const int* __restrict__ et,
       float* __restrict__ agg,
       int E)
{
    int e = blockIdx.x * 8 + (threadIdx.x >> 5);
    if (e >= E) return;
    int lane = threadIdx.x & 31;

    int   s = __ldg(src + e);
    int   d = __ldg(dst + e);
    int   t = __ldg(et + e);
    float n = __ldg(enorm + e);

    int c = lane * 4;
    float4 a = *(const float4*)(hW   + (size_t)s * 128 + c);
    float4 b = *(const float4*)(relW + (size_t)t * 128 + c);
    float4 v = make_float4((a.x + b.x) * n, (a.y + b.y) * n,
                           (a.z + b.z) * n, (a.w + b.w) * n);
    float* p = agg + (size_t)d * 128 + c;
    asm volatile("red.global.add.v4.f32 [%0], {%1,%2,%3,%4};"
                 :: "l"(p), "f"(v.x), "f"(v.y), "f"(v.z), "f"(v.w)
                 : "memory");
}

// ---------------------------------------------------------------------------
extern "C" void kernel_launch(void* const* d_in, const int* in_sizes, int n_in,
                              void* d_out, int out_size)
{
    const float* ent   = (const float*)d_in[0];
    const float* rel   = (const float*)d_in[1];
    const float* his   = (const float*)d_in[2];
    const float* Wn    = (const float*)d_in[3];
    const float* Ws    = (const float*)d_in[4];
    const float* Wt    = (const float*)d_in[5];
    const float* bias  = (const float*)d_in[6];
    const float* enorm = (const float*)d_in[7];
    const int*   src   = (const int*)d_in[8];
    const int*   dst   = (const int*)d_in[9];
    const int*   et    = (const int*)d_in[10];

    int N = in_sizes[0] / DHID;
    int R = in_sizes[1] / DHID;
    int E = in_sizes[7];
    float* out = (float*)d_out;

    float *hW, *relW;
    cudaGetSymbolAddress((void**)&hW, g_hW);
    cudaGetSymbolAddress((void**)&relW, g_relW);

    int dev = 0, sms = 148;
    cudaGetDevice(&dev);
    cudaDeviceGetAttribute(&sms, cudaDevAttrMultiProcessorCount, dev);

    const int numTiles = (N + 127) / 128;
    const int smA = 3 * 128 * PAD * sizeof(float);               // ~198 KB
    const int smD = 2 * 128 * PAD * sizeof(float);               // ~132 KB
    const int smB = (128 * 128 + 64 * 128) * sizeof(float);      //   96 KB
    cudaFuncSetAttribute(k_tensor_dual,  cudaFuncAttributeMaxDynamicSharedMemorySize, smA);
    cudaFuncSetAttribute(k_tensor_final, cudaFuncAttributeMaxDynamicSharedMemorySize, smD);
    cudaFuncSetAttribute(k_rel_gemm,     cudaFuncAttributeMaxDynamicSharedMemorySize, smB);

    k_tensor_dual<<<sms, 512, smA>>>(ent, Wn, Ws, hW, out, N, numTiles);
    k_rel_gemm<<<(R + 63) / 64, 512, smB>>>(rel, Wn, relW, R);
    k_edge<<<(E + 7) / 8, 256>>>(hW, relW, enorm, src, dst, et, out, E);
    k_tensor_final<<<sms, 512, smD>>>(out, Wt, bias, his, N, numTiles);
}

// round 6
// speedup vs baseline: 1.4234x; 1.0751x over previous
#include <cuda_runtime.h>
#include <cuda_fp16.h>
#include <cstdint>
#include <math.h>

#define DHID 128
#define MAX_ENTS 100000
#define MAX_RELS 1000
#define RRELU_SLOPE 0.22916666666666666f
#define PAD 132

typedef uint32_t u32;
typedef unsigned long long ull;

__device__ u32     g_hnorm[MAX_ENTS * DHID];   // tf32 bits of L2-normalized h
__device__ __half2 g_hWh[MAX_ENTS * 64];       // h@Wn, fp16
__device__ __half2 g_relWh[MAX_RELS * 64];     // rel@Wn, fp16

__device__ __forceinline__ u32 f2tf(float x) {
    u32 r; asm("cvt.rna.tf32.f32 %0, %1;" : "=r"(r) : "f"(x)); return r;
}
__device__ __forceinline__ void mma8(float* c, u32 a0, u32 a1, u32 a2, u32 a3,
                                     u32 b0, u32 b1) {
    asm volatile(
        "mma.sync.aligned.m16n8k8.row.col.f32.tf32.tf32.f32 "
        "{%0,%1,%2,%3}, {%4,%5,%6,%7}, {%8,%9}, {%0,%1,%2,%3};"
        : "+f"(c[0]), "+f"(c[1]), "+f"(c[2]), "+f"(c[3])
        : "r"(a0), "r"(a1), "r"(a2), "r"(a3), "r"(b0), "r"(b1));
}

// ---------------------------------------------------------------------------
// k_norm: L2-normalize ent rows -> tf32 bits in g_hnorm. One warp per row.
// ---------------------------------------------------------------------------
extern "C" __global__ void __launch_bounds__(256)
k_norm(const float* __restrict__ ent, u32* __restrict__ out, int N)
{
    int row  = blockIdx.x * 8 + (threadIdx.x >> 5);
    if (row >= N) return;
    int lane = threadIdx.x & 31;
    float4 v = *(const float4*)(ent + (size_t)row * 128 + lane * 4);
    float ss = v.x * v.x + v.y * v.y + v.z * v.z + v.w * v.w;
    #pragma unroll
    for (int off = 16; off > 0; off >>= 1)
        ss += __shfl_xor_sync(0xffffffffu, ss, off);
    float rn = 1.0f / fmaxf(sqrtf(ss), 1e-12f);
    *(uint4*)(out + (size_t)row * 128 + lane * 4) =
        make_uint4(f2tf(v.x * rn), f2tf(v.y * rn), f2tf(v.z * rn), f2tf(v.w * rn));
}

// ---------------------------------------------------------------------------
// k_gemm16: out_fp16[64-row tiles] = A(tf32) @ W. Persistent, 2 CTA/SM.
// 512 thr = 16 warps; warp covers 16 rows x 32 cols (4x m16n8k8 per k-step).
// smem: WT[128][PAD] tf32 | hs[64][PAD] tf32  (101.4 KB)
// ---------------------------------------------------------------------------
extern "C" __global__ void __launch_bounds__(512, 2)
k_gemm16(const u32* __restrict__ A, const float* __restrict__ W,
         __half2* __restrict__ outH, int N, int numTiles)
{
    extern __shared__ u32 smu[];
    u32* WT = smu;               // [n][k]
    u32* hs = smu + 128 * PAD;   // [row][k]
    const int tid  = threadIdx.x;
    const int lane = tid & 31;
    const int w    = tid >> 5;
    const int gid  = lane >> 2;
    const int t4   = lane & 3;

    for (int idx = tid; idx < 128 * 128; idx += 512) {
        int k = idx >> 7, n = idx & 127;
        WT[n * PAD + k] = f2tf(W[idx]);
    }
    __syncthreads();

    const int rb = (w >> 2) * 16;
    const int cb = (w & 3) * 32;

    for (int tile = blockIdx.x; tile < numTiles; tile += gridDim.x) {
        const int base = tile * 64;

        for (int i = tid; i < 64 * 32; i += 512) {
            int row = i >> 5, kq = i & 31, node = base + row;
            uint4 v = make_uint4(0u, 0u, 0u, 0u);
            if (node < N) v = *(const uint4*)(A + (size_t)node * 128 + kq * 4);
            *(uint4*)(hs + row * PAD + kq * 4) = v;
        }
        __syncthreads();

        float acc[4][4];
        #pragma unroll
        for (int nt = 0; nt < 4; nt++)
            #pragma unroll
            for (int i = 0; i < 4; i++) acc[nt][i] = 0.f;

        #pragma unroll
        for (int s = 0; s < 16; s++) {
            const int kb = s * 8;
            u32 a0 = hs[(rb + gid) * PAD + kb + t4];
            u32 a1 = hs[(rb + 8 + gid) * PAD + kb + t4];
            u32 a2 = hs[(rb + gid) * PAD + kb + t4 + 4];
            u32 a3 = hs[(rb + 8 + gid) * PAD + kb + t4 + 4];
            #pragma unroll
            for (int nt = 0; nt < 4; nt++) {
                int c0 = cb + nt * 8 + gid;
                u32 b0 = WT[c0 * PAD + kb + t4];
                u32 b1 = WT[c0 * PAD + kb + t4 + 4];
                mma8(acc[nt], a0, a1, a2, a3, b0, b1);
            }
        }

        #pragma unroll
        for (int nt = 0; nt < 4; nt++) {
            int rl = rb + gid;
            int c  = cb + nt * 8 + 2 * t4;
            int n0 = base + rl, n1 = base + rl + 8;
            if (n0 < N) outH[(size_t)n0 * 64 + (c >> 1)] =
                __floats2half2_rn(acc[nt][0], acc[nt][1]);
            if (n1 < N) outH[(size_t)n1 * 64 + (c >> 1)] =
                __floats2half2_rn(acc[nt][2], acc[nt][3]);
        }
        __syncthreads();
    }
}

// ---------------------------------------------------------------------------
// k_gemm32: same, fp32 output (agg = h@Ws into d_out)
// ---------------------------------------------------------------------------
extern "C" __global__ void __launch_bounds__(512, 2)
k_gemm32(const u32* __restrict__ A, const float* __restrict__ W,
         float* __restrict__ out, int N, int numTiles)
{
    extern __shared__ u32 smu[];
    u32* WT = smu;
    u32* hs = smu + 128 * PAD;
    const int tid  = threadIdx.x;
    const int lane = tid & 31;
    const int w    = tid >> 5;
    const int gid  = lane >> 2;
    const int t4   = lane & 3;

    for (int idx = tid; idx < 128 * 128; idx += 512) {
        int k = idx >> 7, n = idx & 127;
        WT[n * PAD + k] = f2tf(W[idx]);
    }
    __syncthreads();

    const int rb = (w >> 2) * 16;
    const int cb = (w & 3) * 32;

    for (int tile = blockIdx.x; tile < numTiles; tile += gridDim.x) {
        const int base = tile * 64;

        for (int i = tid; i < 64 * 32; i += 512) {
            int row = i >> 5, kq = i & 31, node = base + row;
            uint4 v = make_uint4(0u, 0u, 0u, 0u);
            if (node < N) v = *(const uint4*)(A + (size_t)node * 128 + kq * 4);
            *(uint4*)(hs + row * PAD + kq * 4) = v;
        }
        __syncthreads();

        float acc[4][4];
        #pragma unroll
        for (int nt = 0; nt < 4; nt++)
            #pragma unroll
            for (int i = 0; i < 4; i++) acc[nt][i] = 0.f;

        #pragma unroll
        for (int s = 0; s < 16; s++) {
            const int kb = s * 8;
            u32 a0 = hs[(rb + gid) * PAD + kb + t4];
            u32 a1 = hs[(rb + 8 + gid) * PAD + kb + t4];
            u32 a2 = hs[(rb + gid) * PAD + kb + t4 + 4];
            u32 a3 = hs[(rb + 8 + gid) * PAD + kb + t4 + 4];
            #pragma unroll
            for (int nt = 0; nt < 4; nt++) {
                int c0 = cb + nt * 8 + gid;
                u32 b0 = WT[c0 * PAD + kb + t4];
                u32 b1 = WT[c0 * PAD + kb + t4 + 4];
                mma8(acc[nt], a0, a1, a2, a3, b0, b1);
            }
        }

        #pragma unroll
        for (int nt = 0; nt < 4; nt++) {
            int rl = rb + gid;
            int c  = cb + nt * 8 + 2 * t4;
            int n0 = base + rl, n1 = base + rl + 8;
            if (n0 < N) *(float2*)(out + (size_t)n0 * 128 + c) =
                make_float2(acc[nt][0], acc[nt][1]);
            if (n1 < N) *(float2*)(out + (size_t)n1 * 128 + c) =
                make_float2(acc[nt][2], acc[nt][3]);
        }
        __syncthreads();
    }
}

// ---------------------------------------------------------------------------
// k_rel_gemm: relW(fp16) = rel_emb @ W_neighbor (tiny, SIMT f32x2)
// ---------------------------------------------------------------------------
__device__ __forceinline__ void ffma2(ull& d, ull a, ull b) {
    asm("fma.rn.f32x2 %0, %1, %2, %3;" : "=l"(d) : "l"(a), "l"(b), "l"(d));
}
__device__ __forceinline__ ull pack2(float x, float y) {
    ull r; asm("mov.b64 %0, {%1, %2};" : "=l"(r) : "f"(x), "f"(y)); return r;
}
__device__ __forceinline__ void unpack2(ull v, float& x, float& y) {
    asm("mov.b64 {%0, %1}, %2;" : "=f"(x), "=f"(y) : "l"(v));
}

extern "C" __global__ void __launch_bounds__(512)
k_rel_gemm(const float* __restrict__ rel,
           const float* __restrict__ Wn,
           __half2* __restrict__ relWh,
           int R)
{
    extern __shared__ float sm[];
    float* Wsh = sm;
    float* hsr = sm + 128 * 128;
    const int tid  = threadIdx.x;
    const int base = blockIdx.x * 64;
    const int lane = tid & 31;
    const int w    = tid >> 5;

    for (int t = tid; t < (128 * 128) / 4; t += 512)
        *(float4*)(Wsh + t * 4) = *(const float4*)(Wn + t * 4);

    #pragma unroll
    for (int rr = 0; rr < 4; rr++) {
        int row = w * 4 + rr;
        int r   = base + row;
        float4 v = make_float4(0.f, 0.f, 0.f, 0.f);
        if (r < R) v = *(const float4*)(rel + (size_t)r * 128 + lane * 4);
        *(float4*)(hsr + row * 128 + lane * 4) = v;
    }
    __syncthreads();

    const int r0 = w * 4;
    ull acc[4][2];
    #pragma unroll
    for (int j = 0; j < 4; j++) acc[j][0] = acc[j][1] = 0ull;

    #pragma unroll 2
    for (int kk = 0; kk < 128; kk += 4) {
        float a[4][4];
        #pragma unroll
        for (int j = 0; j < 4; j++) {
            float4 v = *(const float4*)(hsr + (r0 + j) * 128 + kk);
            a[j][0] = v.x; a[j][1] = v.y; a[j][2] = v.z; a[j][3] = v.w;
        }
        #pragma unroll
        for (int t = 0; t < 4; t++) {
            float4 b = *(const float4*)(Wsh + (kk + t) * 128 + lane * 4);
            ull b0 = pack2(b.x, b.y), b1 = pack2(b.z, b.w);
            #pragma unroll
            for (int j = 0; j < 4; j++) {
                ull ap = pack2(a[j][t], a[j][t]);
                ffma2(acc[j][0], ap, b0);
                ffma2(acc[j][1], ap, b1);
            }
        }
    }

    #pragma unroll
    for (int j = 0; j < 4; j++) {
        int r = base + r0 + j;
        if (r >= R) continue;
        float4 o;
        unpack2(acc[j][0], o.x, o.y); unpack2(acc[j][1], o.z, o.w);
        __half2 p0 = __floats2half2_rn(o.x, o.y);
        __half2 p1 = __floats2half2_rn(o.z, o.w);
        uint2 st = make_uint2(*(u32*)&p0, *(u32*)&p1);
        *(uint2*)(relWh + (size_t)r * 64 + lane * 2) = st;
    }
}

// ---------------------------------------------------------------------------
// k_edge: fp16 gathers, fp32 vector-RED scatter. One warp per edge.
// ---------------------------------------------------------------------------
extern "C" __global__ void __launch_bounds__(256)
k_edge(const __half2* __restrict__ hWh,
       const __half2* __restrict__ relWh,
       const float* __restrict__ enorm,
       const int* __restrict__ src,
       const int* __restrict__ dst,
       const int* __restrict__ et,
       float* __restrict__ agg,
       int E)
{
    int e = blockIdx.x * 8 + (threadIdx.x >> 5);
    if (e >= E) return;
    int lane = threadIdx.x & 31;

    int   s = __ldg(src + e);
    int   d = __ldg(dst + e);
    int   t = __ldg(et + e);
    float n = __ldg(enorm + e);

    uint2 ar = *(const uint2*)(hWh   + (size_t)s * 64 + lane * 2);
    uint2 br = *(const uint2*)(relWh + (size_t)t * 64 + lane * 2);
    float2 a0 = __half22float2(*(__half2*)&ar.x);
    float2 a1 = __half22float2(*(__half2*)&ar.y);
    float2 b0 = __half22float2(*(__half2*)&br.x);
    float2 b1 = __half22float2(*(__half2*)&br.y);
    float4 v = make_float4((a0.x + b0.x) * n, (a0.y + b0.y) * n,
                           (a1.x + b1.x) * n, (a1.y + b1.y) * n);
    float* p = agg + (size_t)d * 128 + lane * 4;
    asm volatile("red.global.add.v4.f32 [%0], {%1,%2,%3,%4};"
                 :: "l"(p), "f"(v.x), "f"(v.y), "f"(v.z), "f"(v.w)
                 : "memory");
}

// ---------------------------------------------------------------------------
// k_final: h_cur = rrelu(agg); gate = sigmoid(h_cur@Wt + b);
// out = gate*h_cur + (1-gate)*his. Persistent, 2 CTA/SM, 64-row tiles.
// smem: WT[128][PAD] tf32 | hs[64][PAD] fp32
// ---------------------------------------------------------------------------
extern "C" __global__ void __launch_bounds__(512, 2)
k_final(float* __restrict__ x,
        const float* __restrict__ Wt,
        const float* __restrict__ bias,
        const float* __restrict__ his,
        int N, int numTiles)
{
    extern __shared__ float sm[];
    u32*   WT = (u32*)sm;          // [n][k] tf32
    float* hs = sm + 128 * PAD;    // [row][k] fp32 (post-rrelu)
    const int tid  = threadIdx.x;
    const int lane = tid & 31;
    const int w    = tid >> 5;
    const int gid  = lane >> 2;
    const int t4   = lane & 3;

    for (int idx = tid; idx < 128 * 128; idx += 512) {
        int k = idx >> 7, n = idx & 127;
        WT[n * PAD + k] = f2tf(Wt[idx]);
    }
    __syncthreads();

    const int rb = (w >> 2) * 16;
    const int cb = (w & 3) * 32;

    for (int tile = blockIdx.x; tile < numTiles; tile += gridDim.x) {
        const int base = tile * 64;

        for (int i = tid; i < 64 * 32; i += 512) {
            int row = i >> 5, kq = i & 31, node = base + row;
            float4 v = make_float4(0.f, 0.f, 0.f, 0.f);
            if (node < N) v = *(const float4*)(x + (size_t)node * 128 + kq * 4);
            v.x = v.x >= 0.f ? v.x : RRELU_SLOPE * v.x;
            v.y = v.y >= 0.f ? v.y : RRELU_SLOPE * v.y;
            v.z = v.z >= 0.f ? v.z : RRELU_SLOPE * v.z;
            v.w = v.w >= 0.f ? v.w : RRELU_SLOPE * v.w;
            *(float4*)(hs + row * PAD + kq * 4) = v;
        }
        __syncthreads();

        float acc[4][4];
        #pragma unroll
        for (int nt = 0; nt < 4; nt++)
            #pragma unroll
            for (int i = 0; i < 4; i++) acc[nt][i] = 0.f;

        #pragma unroll
        for (int s = 0; s < 16; s++) {
            const int kb = s * 8;
            u32 a0 = f2tf(hs[(rb + gid) * PAD + kb + t4]);
            u32 a1 = f2tf(hs[(rb + 8 + gid) * PAD + kb + t4]);
            u32 a2 = f2tf(hs[(rb + gid) * PAD + kb + t4 + 4]);
            u32 a3 = f2tf(hs[(rb + 8 + gid) * PAD + kb + t4 + 4]);
            #pragma unroll
            for (int nt = 0; nt < 4; nt++) {
                int c0 = cb + nt * 8 + gid;
                u32 b0 = WT[c0 * PAD + kb + t4];
                u32 b1 = WT[c0 * PAD + kb + t4 + 4];
                mma8(acc[nt], a0, a1, a2, a3, b0, b1);
            }
        }

        #pragma unroll
        for (int nt = 0; nt < 4; nt++) {
            int rl = rb + gid;
            int c  = cb + nt * 8 + 2 * t4;
            float2 bv = *(const float2*)(bias + c);
            #pragma unroll
            for (int half = 0; half < 2; half++) {
                int row  = rl + half * 8;
                int node = base + row;
                if (node >= N) continue;
                float l0 = acc[nt][half * 2 + 0] + bv.x;
                float l1 = acc[nt][half * 2 + 1] + bv.y;
                float s0 = 1.0f / (1.0f + __expf(-l0));
                float s1 = 1.0f / (1.0f + __expf(-l1));
                float2 hv = *(const float2*)(hs + row * PAD + c);
                float2 hh = *(const float2*)(his + (size_t)node * 128 + c);
                float2 o = make_float2(s0 * hv.x + (1.f - s0) * hh.x,
                                       s1 * hv.y + (1.f - s1) * hh.y);
                *(float2*)(x + (size_t)node * 128 + c) = o;
            }
        }
        __syncthreads();
    }
}

// ---------------------------------------------------------------------------
extern "C" void kernel_launch(void* const* d_in, const int* in_sizes, int n_in,
                              void* d_out, int out_size)
{
    const float* ent   = (const float*)d_in[0];
    const float* rel   = (const float*)d_in[1];
    const float* his   = (const float*)d_in[2];
    const float* Wn    = (const float*)d_in[3];
    const float* Ws    = (const float*)d_in[4];
    const float* Wt    = (const float*)d_in[5];
    const float* bias  = (const float*)d_in[6];
    const float* enorm = (const float*)d_in[7];
    const int*   src   = (const int*)d_in[8];
    const int*   dst   = (const int*)d_in[9];
    const int*   et    = (const int*)d_in[10];

    int N = in_sizes[0] / DHID;
    int R = in_sizes[1] / DHID;
    int E = in_sizes[7];
    float* out = (float*)d_out;

    u32 *hnorm; __half2 *hWh, *relWh;
    cudaGetSymbolAddress((void**)&hnorm, g_hnorm);
    cudaGetSymbolAddress((void**)&hWh,   g_hWh);
    cudaGetSymbolAddress((void**)&relWh, g_relWh);

    int dev = 0, sms = 148;
    cudaGetDevice(&dev);
    cudaDeviceGetAttribute(&sms, cudaDevAttrMultiProcessorCount, dev);

    const int numTiles = (N + 63) / 64;
    const int smG = (128 * PAD + 64 * PAD) * sizeof(float);   // ~101.4 KB
    const int smB = (128 * 128 + 64 * 128) * sizeof(float);   //   96 KB
    cudaFuncSetAttribute(k_gemm16, cudaFuncAttributeMaxDynamicSharedMemorySize, smG);
    cudaFuncSetAttribute(k_gemm32, cudaFuncAttributeMaxDynamicSharedMemorySize, smG);
    cudaFuncSetAttribute(k_final,  cudaFuncAttributeMaxDynamicSharedMemorySize, smG);
    cudaFuncSetAttribute(k_rel_gemm, cudaFuncAttributeMaxDynamicSharedMemorySize, smB);

    k_norm<<<(N + 7) / 8, 256>>>(ent, hnorm, N);
    k_gemm16<<<2 * sms, 512, smG>>>(hnorm, Wn, hWh, N, numTiles);
    k_gemm32<<<2 * sms, 512, smG>>>(hnorm, Ws, out, N, numTiles);
    k_rel_gemm<<<(R + 63) / 64, 512, smB>>>(rel, Wn, relWh, R);
    k_edge<<<(E + 7) / 8, 256>>>(hWh, relWh, enorm, src, dst, et, out, E);
    k_final<<<2 * sms, 512, smG>>>(out, Wt, bias, his, N, numTiles);
}

// round 7
// speedup vs baseline: 1.8181x; 1.2773x over previous
#include <cuda_runtime.h>
#include <cuda_fp16.h>
#include <cstdint>
#include <math.h>

#define DHID 128
#define MAX_ENTS 100000
#define MAX_RELS 1000
#define MAX_EDGES 2000000
#define RRELU_SLOPE 0.22916666666666666f
#define PAD 132

typedef uint32_t u32;

__device__ u32     g_hnorm[MAX_ENTS * DHID];     // tf32 bits of normalized h
__device__ __half2 g_hWh[MAX_ENTS * 64];         // h@Wn fp16
__device__ __half2 g_relWh[MAX_RELS * 64];       // rel@Wn fp16
__device__ int     g_cnt[MAX_ENTS];              // per-dst edge counts
__device__ int     g_off[MAX_ENTS];              // bucket start offsets
__device__ int     g_cur[MAX_ENTS];              // scatter cursors
__device__ int     g_bsum[256];                  // scan partials
__device__ uint4   g_rec[MAX_EDGES];             // (src, et, norm_bits, 0)

__device__ __forceinline__ u32 f2tf(float x) {
    u32 r; asm("cvt.rna.tf32.f32 %0, %1;" : "=r"(r) : "f"(x)); return r;
}
__device__ __forceinline__ void mma8(float* c, u32 a0, u32 a1, u32 a2, u32 a3,
                                     u32 b0, u32 b1) {
    asm volatile(
        "mma.sync.aligned.m16n8k8.row.col.f32.tf32.tf32.f32 "
        "{%0,%1,%2,%3}, {%4,%5,%6,%7}, {%8,%9}, {%0,%1,%2,%3};"
        : "+f"(c[0]), "+f"(c[1]), "+f"(c[2]), "+f"(c[3])
        : "r"(a0), "r"(a1), "r"(a2), "r"(a3), "r"(b0), "r"(b1));
}

// ---------------------------------------------------------------------------
extern "C" __global__ void k_zero(int* __restrict__ p, int n) {
    int i = blockIdx.x * 1024 + threadIdx.x;
    if (i < n) p[i] = 0;
}

// L2-normalize -> tf32 bits. One warp per row.
extern "C" __global__ void __launch_bounds__(256)
k_norm(const float* __restrict__ ent, u32* __restrict__ out, int N)
{
    int row  = blockIdx.x * 8 + (threadIdx.x >> 5);
    if (row >= N) return;
    int lane = threadIdx.x & 31;
    float4 v = *(const float4*)(ent + (size_t)row * 128 + lane * 4);
    float ss = v.x * v.x + v.y * v.y + v.z * v.z + v.w * v.w;
    #pragma unroll
    for (int off = 16; off > 0; off >>= 1)
        ss += __shfl_xor_sync(0xffffffffu, ss, off);
    float rn = 1.0f / fmaxf(sqrtf(ss), 1e-12f);
    *(uint4*)(out + (size_t)row * 128 + lane * 4) =
        make_uint4(f2tf(v.x * rn), f2tf(v.y * rn), f2tf(v.z * rn), f2tf(v.w * rn));
}

// ---------------------------------------------------------------------------
// Counting sort of edges by dst
// ---------------------------------------------------------------------------
extern "C" __global__ void __launch_bounds__(256)
k_hist(const int* __restrict__ dst, int E)
{
    int e = blockIdx.x * 256 + threadIdx.x;
    if (e < E) atomicAdd(&g_cnt[dst[e]], 1);
}

extern "C" __global__ void __launch_bounds__(1024)
k_scan1(int N)   // per-block totals of 1024-chunks
{
    __shared__ int smi[1024];
    int i = blockIdx.x * 1024 + threadIdx.x;
    int v = (i < N) ? g_cnt[i] : 0;
    smi[threadIdx.x] = v;
    __syncthreads();
    for (int off = 512; off > 0; off >>= 1) {
        if (threadIdx.x < off) smi[threadIdx.x] += smi[threadIdx.x + off];
        __syncthreads();
    }
    if (threadIdx.x == 0) g_bsum[blockIdx.x] = smi[0];
}

extern "C" __global__ void k_scan2(int nb)   // serial exclusive scan of partials
{
    if (threadIdx.x == 0) {
        int run = 0;
        for (int i = 0; i < nb; i++) { int v = g_bsum[i]; g_bsum[i] = run; run += v; }
    }
}

extern "C" __global__ void __launch_bounds__(1024)
k_scan3(int N)   // block exclusive scan + base -> g_off, g_cur
{
    __shared__ int smi[1024];
    int i = blockIdx.x * 1024 + threadIdx.x;
    int v = (i < N) ? g_cnt[i] : 0;
    smi[threadIdx.x] = v;
    __syncthreads();
    #pragma unroll
    for (int off = 1; off < 1024; off <<= 1) {
        int x = (threadIdx.x >= off) ? smi[threadIdx.x - off] : 0;
        __syncthreads();
        smi[threadIdx.x] += x;
        __syncthreads();
    }
    if (i < N) {
        int ex = smi[threadIdx.x] - v + g_bsum[blockIdx.x];
        g_off[i] = ex;
        g_cur[i] = ex;
    }
}

extern "C" __global__ void __launch_bounds__(256)
k_scatter(const int* __restrict__ src, const int* __restrict__ dst,
          const int* __restrict__ et, const float* __restrict__ enorm, int E)
{
    int e = blockIdx.x * 256 + threadIdx.x;
    if (e >= E) return;
    int d   = dst[e];
    int pos = atomicAdd(&g_cur[d], 1);
    g_rec[pos] = make_uint4((u32)src[e], (u32)et[e],
                            __float_as_uint(enorm[e]), 0u);
}

// ---------------------------------------------------------------------------
// k_gemm16: fp16 out = A @ Wn for rows [0,N) = hnorm (tf32 bits) and
// rows [N, N+R) = rel_emb (fp32, converted). Persistent, 2 CTA/SM.
// ---------------------------------------------------------------------------
extern "C" __global__ void __launch_bounds__(512, 2)
k_gemm16(const u32* __restrict__ A, const float* __restrict__ rel,
         const float* __restrict__ W,
         __half2* __restrict__ hWh, __half2* __restrict__ relWh,
         int N, int R, int numTiles)
{
    extern __shared__ u32 smu[];
    u32* WT = smu;               // [n][k] tf32
    u32* hs = smu + 128 * PAD;   // [row][k] tf32
    const int tid  = threadIdx.x;
    const int lane = tid & 31;
    const int w    = tid >> 5;
    const int gid  = lane >> 2;
    const int t4   = lane & 3;

    for (int idx = tid; idx < 128 * 128; idx += 512) {
        int k = idx >> 7, n = idx & 127;
        WT[n * PAD + k] = f2tf(W[idx]);
    }
    __syncthreads();

    const int rb = (w >> 2) * 16;
    const int cb = (w & 3) * 32;

    for (int tile = blockIdx.x; tile < numTiles; tile += gridDim.x) {
        const int base = tile * 64;

        for (int i = tid; i < 64 * 32; i += 512) {
            int row = i >> 5, kq = i & 31, node = base + row;
            uint4 v = make_uint4(0u, 0u, 0u, 0u);
            if (node < N) {
                v = *(const uint4*)(A + (size_t)node * 128 + kq * 4);
            } else if (node < N + R) {
                float4 f = *(const float4*)(rel + (size_t)(node - N) * 128 + kq * 4);
                v = make_uint4(f2tf(f.x), f2tf(f.y), f2tf(f.z), f2tf(f.w));
            }
            *(uint4*)(hs + row * PAD + kq * 4) = v;
        }
        __syncthreads();

        float acc[4][4];
        #pragma unroll
        for (int nt = 0; nt < 4; nt++)
            #pragma unroll
            for (int i = 0; i < 4; i++) acc[nt][i] = 0.f;

        #pragma unroll
        for (int s = 0; s < 16; s++) {
            const int kb = s * 8;
            u32 a0 = hs[(rb + gid) * PAD + kb + t4];
            u32 a1 = hs[(rb + 8 + gid) * PAD + kb + t4];
            u32 a2 = hs[(rb + gid) * PAD + kb + t4 + 4];
            u32 a3 = hs[(rb + 8 + gid) * PAD + kb + t4 + 4];
            #pragma unroll
            for (int nt = 0; nt < 4; nt++) {
                int c0 = cb + nt * 8 + gid;
                u32 b0 = WT[c0 * PAD + kb + t4];
                u32 b1 = WT[c0 * PAD + kb + t4 + 4];
                mma8(acc[nt], a0, a1, a2, a3, b0, b1);
            }
        }

        #pragma unroll
        for (int nt = 0; nt < 4; nt++) {
            int rl = rb + gid;
            int c  = cb + nt * 8 + 2 * t4;
            #pragma unroll
            for (int half = 0; half < 2; half++) {
                int node = base + rl + half * 8;
                __half2 p = __floats2half2_rn(acc[nt][half * 2], acc[nt][half * 2 + 1]);
                if (node < N)              g_hWh[(size_t)node * 64 + (c >> 1)] = p;
                else if (node < N + R)     g_relWh[(size_t)(node - N) * 64 + (c >> 1)] = p;
            }
        }
        __syncthreads();
    }
}

// ---------------------------------------------------------------------------
// k_gemm32: agg(d_out) = hnorm @ Ws. Persistent, 2 CTA/SM.
// ---------------------------------------------------------------------------
extern "C" __global__ void __launch_bounds__(512, 2)
k_gemm32(const u32* __restrict__ A, const float* __restrict__ W,
         float* __restrict__ out, int N, int numTiles)
{
    extern __shared__ u32 smu[];
    u32* WT = smu;
    u32* hs = smu + 128 * PAD;
    const int tid  = threadIdx.x;
    const int lane = tid & 31;
    const int w    = tid >> 5;
    const int gid  = lane >> 2;
    const int t4   = lane & 3;

    for (int idx = tid; idx < 128 * 128; idx += 512) {
        int k = idx >> 7, n = idx & 127;
        WT[n * PAD + k] = f2tf(W[idx]);
    }
    __syncthreads();

    const int rb = (w >> 2) * 16;
    const int cb = (w & 3) * 32;

    for (int tile = blockIdx.x; tile < numTiles; tile += gridDim.x) {
        const int base = tile * 64;

        for (int i = tid; i < 64 * 32; i += 512) {
            int row = i >> 5, kq = i & 31, node = base + row;
            uint4 v = make_uint4(0u, 0u, 0u, 0u);
            if (node < N) v = *(const uint4*)(A + (size_t)node * 128 + kq * 4);
            *(uint4*)(hs + row * PAD + kq * 4) = v;
        }
        __syncthreads();

        float acc[4][4];
        #pragma unroll
        for (int nt = 0; nt < 4; nt++)
            #pragma unroll
            for (int i = 0; i < 4; i++) acc[nt][i] = 0.f;

        #pragma unroll
        for (int s = 0; s < 16; s++) {
            const int kb = s * 8;
            u32 a0 = hs[(rb + gid) * PAD + kb + t4];
            u32 a1 = hs[(rb + 8 + gid) * PAD + kb + t4];
            u32 a2 = hs[(rb + gid) * PAD + kb + t4 + 4];
            u32 a3 = hs[(rb + 8 + gid) * PAD + kb + t4 + 4];
            #pragma unroll
            for (int nt = 0; nt < 4; nt++) {
                int c0 = cb + nt * 8 + gid;
                u32 b0 = WT[c0 * PAD + kb + t4];
                u32 b1 = WT[c0 * PAD + kb + t4 + 4];
                mma8(acc[nt], a0, a1, a2, a3, b0, b1);
            }
        }

        #pragma unroll
        for (int nt = 0; nt < 4; nt++) {
            int rl = rb + gid;
            int c  = cb + nt * 8 + 2 * t4;
            int n0 = base + rl, n1 = base + rl + 8;
            if (n0 < N) *(float2*)(out + (size_t)n0 * 128 + c) =
                make_float2(acc[nt][0], acc[nt][1]);
            if (n1 < N) *(float2*)(out + (size_t)n1 * 128 + c) =
                make_float2(acc[nt][2], acc[nt][3]);
        }
        __syncthreads();
    }
}

// ---------------------------------------------------------------------------
// k_agg: warp per dst. acc = d_out[d] (h@Ws), += (hW[src]+relW[et])*norm over
// the dst's sorted edge records. No atomics.
// ---------------------------------------------------------------------------
extern "C" __global__ void __launch_bounds__(256)
k_agg(float* __restrict__ out, int N)
{
    int d = blockIdx.x * 8 + (threadIdx.x >> 5);
    if (d >= N) return;
    int lane = threadIdx.x & 31;

    float4 acc = *(const float4*)(out + (size_t)d * 128 + lane * 4);
    const int s0  = g_off[d];
    const int cnt = g_cnt[d];

    int i = 0;
    for (; i + 2 <= cnt; i += 2) {
        uint4 r0 = g_rec[s0 + i];
        uint4 r1 = g_rec[s0 + i + 1];
        uint2 a0 = *(const uint2*)(g_hWh   + (size_t)r0.x * 64 + lane * 2);
        uint2 b0 = *(const uint2*)(g_relWh + (size_t)r0.y * 64 + lane * 2);
        uint2 a1 = *(const uint2*)(g_hWh   + (size_t)r1.x * 64 + lane * 2);
        uint2 b1 = *(const uint2*)(g_relWh + (size_t)r1.y * 64 + lane * 2);
        float n0 = __uint_as_float(r0.z);
        float n1 = __uint_as_float(r1.z);
        float2 ax = __half22float2(*(__half2*)&a0.x), ay = __half22float2(*(__half2*)&a0.y);
        float2 bx = __half22float2(*(__half2*)&b0.x), by = __half22float2(*(__half2*)&b0.y);
        acc.x += (ax.x + bx.x) * n0; acc.y += (ax.y + bx.y) * n0;
        acc.z += (ay.x + by.x) * n0; acc.w += (ay.y + by.y) * n0;
        ax = __half22float2(*(__half2*)&a1.x); ay = __half22float2(*(__half2*)&a1.y);
        bx = __half22float2(*(__half2*)&b1.x); by = __half22float2(*(__half2*)&b1.y);
        acc.x += (ax.x + bx.x) * n1; acc.y += (ax.y + bx.y) * n1;
        acc.z += (ay.x + by.x) * n1; acc.w += (ay.y + by.y) * n1;
    }
    if (i < cnt) {
        uint4 r = g_rec[s0 + i];
        uint2 a = *(const uint2*)(g_hWh   + (size_t)r.x * 64 + lane * 2);
        uint2 b = *(const uint2*)(g_relWh + (size_t)r.y * 64 + lane * 2);
        float n = __uint_as_float(r.z);
        float2 ax = __half22float2(*(__half2*)&a.x), ay = __half22float2(*(__half2*)&a.y);
        float2 bx = __half22float2(*(__half2*)&b.x), by = __half22float2(*(__half2*)&b.y);
        acc.x += (ax.x + bx.x) * n; acc.y += (ax.y + bx.y) * n;
        acc.z += (ay.x + by.x) * n; acc.w += (ay.y + by.y) * n;
    }
    *(float4*)(out + (size_t)d * 128 + lane * 4) = acc;
}

// ---------------------------------------------------------------------------
// k_final: h_cur = rrelu(agg); gate = sigmoid(h_cur@Wt + b);
// out = gate*h_cur + (1-gate)*his. Persistent, 2 CTA/SM, 64-row tiles.
// ---------------------------------------------------------------------------
extern "C" __global__ void __launch_bounds__(512, 2)
k_final(float* __restrict__ x,
        const float* __restrict__ Wt,
        const float* __restrict__ bias,
        const float* __restrict__ his,
        int N, int numTiles)
{
    extern __shared__ float sm[];
    u32*   WT = (u32*)sm;          // [n][k] tf32
    float* hs = sm + 128 * PAD;    // [row][k] fp32 post-rrelu
    const int tid  = threadIdx.x;
    const int lane = tid & 31;
    const int w    = tid >> 5;
    const int gid  = lane >> 2;
    const int t4   = lane & 3;

    for (int idx = tid; idx < 128 * 128; idx += 512) {
        int k = idx >> 7, n = idx & 127;
        WT[n * PAD + k] = f2tf(Wt[idx]);
    }
    __syncthreads();

    const int rb = (w >> 2) * 16;
    const int cb = (w & 3) * 32;

    for (int tile = blockIdx.x; tile < numTiles; tile += gridDim.x) {
        const int base = tile * 64;

        for (int i = tid; i < 64 * 32; i += 512) {
            int row = i >> 5, kq = i & 31, node = base + row;
            float4 v = make_float4(0.f, 0.f, 0.f, 0.f);
            if (node < N) v = *(const float4*)(x + (size_t)node * 128 + kq * 4);
            v.x = v.x >= 0.f ? v.x : RRELU_SLOPE * v.x;
            v.y = v.y >= 0.f ? v.y : RRELU_SLOPE * v.y;
            v.z = v.z >= 0.f ? v.z : RRELU_SLOPE * v.z;
            v.w = v.w >= 0.f ? v.w : RRELU_SLOPE * v.w;
            *(float4*)(hs + row * PAD + kq * 4) = v;
        }
        __syncthreads();

        float acc[4][4];
        #pragma unroll
        for (int nt = 0; nt < 4; nt++)
            #pragma unroll
            for (int i = 0; i < 4; i++) acc[nt][i] = 0.f;

        #pragma unroll
        for (int s = 0; s < 16; s++) {
            const int kb = s * 8;
            u32 a0 = f2tf(hs[(rb + gid) * PAD + kb + t4]);
            u32 a1 = f2tf(hs[(rb + 8 + gid) * PAD + kb + t4]);
            u32 a2 = f2tf(hs[(rb + gid) * PAD + kb + t4 + 4]);
            u32 a3 = f2tf(hs[(rb + 8 + gid) * PAD + kb + t4 + 4]);
            #pragma unroll
            for (int nt = 0; nt < 4; nt++) {
                int c0 = cb + nt * 8 + gid;
                u32 b0 = WT[c0 * PAD + kb + t4];
                u32 b1 = WT[c0 * PAD + kb + t4 + 4];
                mma8(acc[nt], a0, a1, a2, a3, b0, b1);
            }
        }

        #pragma unroll
        for (int nt = 0; nt < 4; nt++) {
            int rl = rb + gid;
            int c  = cb + nt * 8 + 2 * t4;
            float2 bv = *(const float2*)(bias + c);
            #pragma unroll
            for (int half = 0; half < 2; half++) {
                int row  = rl + half * 8;
                int node = base + row;
                if (node >= N) continue;
                float l0 = acc[nt][half * 2 + 0] + bv.x;
                float l1 = acc[nt][half * 2 + 1] + bv.y;
                float s0 = 1.0f / (1.0f + __expf(-l0));
                float s1 = 1.0f / (1.0f + __expf(-l1));
                float2 hv = *(const float2*)(hs + row * PAD + c);
                float2 hh = *(const float2*)(his + (size_t)node * 128 + c);
                float2 o = make_float2(s0 * hv.x + (1.f - s0) * hh.x,
                                       s1 * hv.y + (1.f - s1) * hh.y);
                *(float2*)(x + (size_t)node * 128 + c) = o;
            }
        }
        __syncthreads();
    }
}

// ---------------------------------------------------------------------------
extern "C" void kernel_launch(void* const* d_in, const int* in_sizes, int n_in,
                              void* d_out, int out_size)
{
    const float* ent   = (const float*)d_in[0];
    const float* rel   = (const float*)d_in[1];
    const float* his   = (const float*)d_in[2];
    const float* Wn    = (const float*)d_in[3];
    const float* Ws    = (const float*)d_in[4];
    const float* Wt    = (const float*)d_in[5];
    const float* bias  = (const float*)d_in[6];
    const float* enorm = (const float*)d_in[7];
    const int*   src   = (const int*)d_in[8];
    const int*   dst   = (const int*)d_in[9];
    const int*   et    = (const int*)d_in[10];

    int N = in_sizes[0] / DHID;
    int R = in_sizes[1] / DHID;
    int E = in_sizes[7];
    float* out = (float*)d_out;

    u32 *hnorm; __half2 *hWh, *relWh; int* cnt;
    cudaGetSymbolAddress((void**)&hnorm, g_hnorm);
    cudaGetSymbolAddress((void**)&hWh,   g_hWh);
    cudaGetSymbolAddress((void**)&relWh, g_relWh);
    cudaGetSymbolAddress((void**)&cnt,   g_cnt);

    int dev = 0, sms = 148;
    cudaGetDevice(&dev);
    cudaDeviceGetAttribute(&sms, cudaDevAttrMultiProcessorCount, dev);

    const int numTiles  = (N + 63) / 64;
    const int numTilesG = (N + R + 63) / 64;
    const int nb        = (N + 1023) / 1024;
    const int smG = (128 * PAD + 64 * PAD) * sizeof(float);   // ~101.4 KB
    cudaFuncSetAttribute(k_gemm16, cudaFuncAttributeMaxDynamicSharedMemorySize, smG);
    cudaFuncSetAttribute(k_gemm32, cudaFuncAttributeMaxDynamicSharedMemorySize, smG);
    cudaFuncSetAttribute(k_final,  cudaFuncAttributeMaxDynamicSharedMemorySize, smG);

    // Sort edges by dst (counting sort)
    k_zero<<<nb, 1024>>>(cnt, N);
    k_hist<<<(E + 255) / 256, 256>>>(dst, E);
    k_scan1<<<nb, 1024>>>(N);
    k_scan2<<<1, 32>>>(nb);
    k_scan3<<<nb, 1024>>>(N);
    k_scatter<<<(E + 255) / 256, 256>>>(src, dst, et, enorm, E);

    // Node pipeline
    k_norm<<<(N + 7) / 8, 256>>>(ent, hnorm, N);
    k_gemm16<<<2 * sms, 512, smG>>>(hnorm, rel, Wn, hWh, relWh, N, R, numTilesG);
    k_gemm32<<<2 * sms, 512, smG>>>(hnorm, Ws, out, N, numTiles);
    k_agg<<<(N + 7) / 8, 256>>>(out, N);
    k_final<<<2 * sms, 512, smG>>>(out, Wt, bias, his, N, numTiles);
}

// round 8
// speedup vs baseline: 1.8875x; 1.0382x over previous
#include <cuda_runtime.h>
#include <cuda_fp16.h>
#include <cstdint>
#include <math.h>

#define DHID 128
#define MAX_ENTS 100000
#define MAX_RELS 1000
#define MAX_EDGES 2000000
#define RRELU_SLOPE 0.22916666666666666f
#define PAD 132

typedef uint32_t u32;

__device__ __half2 g_hWh[MAX_ENTS * 64];         // h@Wn fp16
__device__ __half2 g_relWh[MAX_RELS * 64];       // rel@Wn fp16
__device__ int     g_cnt[MAX_ENTS];              // per-dst edge counts
__device__ int     g_off[MAX_ENTS];              // bucket start offsets
__device__ int     g_cur[MAX_ENTS];              // scatter cursors
__device__ int     g_bsum[256];                  // scan partials
__device__ uint2   g_rec[MAX_EDGES];             // (src | et<<17, norm_bits)

__device__ __forceinline__ u32 f2tf(float x) {
    u32 r; asm("cvt.rna.tf32.f32 %0, %1;" : "=r"(r) : "f"(x)); return r;
}
__device__ __forceinline__ void mma8(float* c, u32 a0, u32 a1, u32 a2, u32 a3,
                                     u32 b0, u32 b1) {
    asm volatile(
        "mma.sync.aligned.m16n8k8.row.col.f32.tf32.tf32.f32 "
        "{%0,%1,%2,%3}, {%4,%5,%6,%7}, {%8,%9}, {%0,%1,%2,%3};"
        : "+f"(c[0]), "+f"(c[1]), "+f"(c[2]), "+f"(c[3])
        : "r"(a0), "r"(a1), "r"(a2), "r"(a3), "r"(b0), "r"(b1));
}

// ---------------------------------------------------------------------------
// Edge counting sort by dst
// ---------------------------------------------------------------------------
extern "C" __global__ void k_zero(int* __restrict__ p, int n) {
    int i = blockIdx.x * 1024 + threadIdx.x;
    if (i < n) p[i] = 0;
}

extern "C" __global__ void __launch_bounds__(256)
k_hist(const int* __restrict__ dst, int E)
{
    int e = blockIdx.x * 256 + threadIdx.x;
    if (e < E) atomicAdd(&g_cnt[dst[e]], 1);
}

extern "C" __global__ void __launch_bounds__(1024)
k_scan1(int N)
{
    __shared__ int smi[1024];
    int i = blockIdx.x * 1024 + threadIdx.x;
    int v = (i < N) ? g_cnt[i] : 0;
    smi[threadIdx.x] = v;
    __syncthreads();
    for (int off = 512; off > 0; off >>= 1) {
        if (threadIdx.x < off) smi[threadIdx.x] += smi[threadIdx.x + off];
        __syncthreads();
    }
    if (threadIdx.x == 0) g_bsum[blockIdx.x] = smi[0];
}

extern "C" __global__ void __launch_bounds__(256)
k_scan2(int nb)
{
    __shared__ int s[256];
    int t = threadIdx.x;
    int v = (t < nb) ? g_bsum[t] : 0;
    s[t] = v;
    __syncthreads();
    #pragma unroll
    for (int off = 1; off < 256; off <<= 1) {
        int x = (t >= off) ? s[t - off] : 0;
        __syncthreads();
        s[t] += x;
        __syncthreads();
    }
    if (t < nb) g_bsum[t] = s[t] - v;   // exclusive
}

extern "C" __global__ void __launch_bounds__(1024)
k_scan3(int N)
{
    __shared__ int smi[1024];
    int i = blockIdx.x * 1024 + threadIdx.x;
    int v = (i < N) ? g_cnt[i] : 0;
    smi[threadIdx.x] = v;
    __syncthreads();
    #pragma unroll
    for (int off = 1; off < 1024; off <<= 1) {
        int x = (threadIdx.x >= off) ? smi[threadIdx.x - off] : 0;
        __syncthreads();
        smi[threadIdx.x] += x;
        __syncthreads();
    }
    if (i < N) {
        int ex = smi[threadIdx.x] - v + g_bsum[blockIdx.x];
        g_off[i] = ex;
        g_cur[i] = ex;
    }
}

extern "C" __global__ void __launch_bounds__(256)
k_scatter(const int* __restrict__ src, const int* __restrict__ dst,
          const int* __restrict__ et, const float* __restrict__ enorm, int E)
{
    int e = blockIdx.x * 256 + threadIdx.x;
    if (e >= E) return;
    int d   = dst[e];
    int pos = atomicAdd(&g_cur[d], 1);
    g_rec[pos] = make_uint2((u32)src[e] | ((u32)et[e] << 17),
                            __float_as_uint(enorm[e]));
}

// ---------------------------------------------------------------------------
// k_gemm16: fp16 out = normalize(ent) @ Wn for rows [0,N); rel rows [N,N+R)
// (no normalization). Normalization fused into load phase (warp per 4 rows).
// Persistent, 2 CTA/SM. smem: WT[128][PAD] | hs[64][PAD] tf32.
// ---------------------------------------------------------------------------
extern "C" __global__ void __launch_bounds__(512, 2)
k_gemm16(const float* __restrict__ ent, const float* __restrict__ rel,
         const float* __restrict__ W, int N, int R, int numTiles)
{
    extern __shared__ u32 smu[];
    u32* WT = smu;               // [n][k] tf32
    u32* hs = smu + 128 * PAD;   // [row][k] tf32
    const int tid  = threadIdx.x;
    const int lane = tid & 31;
    const int w    = tid >> 5;
    const int gid  = lane >> 2;
    const int t4   = lane & 3;

    for (int idx = tid; idx < 128 * 128; idx += 512) {
        int k = idx >> 7, n = idx & 127;
        WT[n * PAD + k] = f2tf(W[idx]);
    }
    __syncthreads();

    const int rb = (w >> 2) * 16;
    const int cb = (w & 3) * 32;

    for (int tile = blockIdx.x; tile < numTiles; tile += gridDim.x) {
        const int base = tile * 64;

        // load + normalize: warp w handles rows 4w..4w+3
        #pragma unroll
        for (int rr = 0; rr < 4; rr++) {
            int row = w * 4 + rr, node = base + row;
            uint4 o = make_uint4(0u, 0u, 0u, 0u);
            if (node < N) {
                float4 v = *(const float4*)(ent + (size_t)node * 128 + lane * 4);
                float ss = v.x * v.x + v.y * v.y + v.z * v.z + v.w * v.w;
                #pragma unroll
                for (int off = 16; off > 0; off >>= 1)
                    ss += __shfl_xor_sync(0xffffffffu, ss, off);
                float rn = 1.0f / fmaxf(sqrtf(ss), 1e-12f);
                o = make_uint4(f2tf(v.x * rn), f2tf(v.y * rn),
                               f2tf(v.z * rn), f2tf(v.w * rn));
            } else if (node < N + R) {
                float4 v = *(const float4*)(rel + (size_t)(node - N) * 128 + lane * 4);
                o = make_uint4(f2tf(v.x), f2tf(v.y), f2tf(v.z), f2tf(v.w));
            }
            *(uint4*)(hs + row * PAD + lane * 4) = o;
        }
        __syncthreads();

        float acc[4][4];
        #pragma unroll
        for (int nt = 0; nt < 4; nt++)
            #pragma unroll
            for (int i = 0; i < 4; i++) acc[nt][i] = 0.f;

        #pragma unroll
        for (int s = 0; s < 16; s++) {
            const int kb = s * 8;
            u32 a0 = hs[(rb + gid) * PAD + kb + t4];
            u32 a1 = hs[(rb + 8 + gid) * PAD + kb + t4];
            u32 a2 = hs[(rb + gid) * PAD + kb + t4 + 4];
            u32 a3 = hs[(rb + 8 + gid) * PAD + kb + t4 + 4];
            #pragma unroll
            for (int nt = 0; nt < 4; nt++) {
                int c0 = cb + nt * 8 + gid;
                u32 b0 = WT[c0 * PAD + kb + t4];
                u32 b1 = WT[c0 * PAD + kb + t4 + 4];
                mma8(acc[nt], a0, a1, a2, a3, b0, b1);
            }
        }

        #pragma unroll
        for (int nt = 0; nt < 4; nt++) {
            int rl = rb + gid;
            int c  = cb + nt * 8 + 2 * t4;
            #pragma unroll
            for (int half = 0; half < 2; half++) {
                int node = base + rl + half * 8;
                __half2 p = __floats2half2_rn(acc[nt][half * 2], acc[nt][half * 2 + 1]);
                if (node < N)          g_hWh[(size_t)node * 64 + (c >> 1)] = p;
                else if (node < N + R) g_relWh[(size_t)(node - N) * 64 + (c >> 1)] = p;
            }
        }
        __syncthreads();
    }
}

// ---------------------------------------------------------------------------
// k_gemm32: d_out = normalize(ent) @ Ws. Norm fused. Persistent, 2 CTA/SM.
// ---------------------------------------------------------------------------
extern "C" __global__ void __launch_bounds__(512, 2)
k_gemm32(const float* __restrict__ ent, const float* __restrict__ W,
         float* __restrict__ out, int N, int numTiles)
{
    extern __shared__ u32 smu[];
    u32* WT = smu;
    u32* hs = smu + 128 * PAD;
    const int tid  = threadIdx.x;
    const int lane = tid & 31;
    const int w    = tid >> 5;
    const int gid  = lane >> 2;
    const int t4   = lane & 3;

    for (int idx = tid; idx < 128 * 128; idx += 512) {
        int k = idx >> 7, n = idx & 127;
        WT[n * PAD + k] = f2tf(W[idx]);
    }
    __syncthreads();

    const int rb = (w >> 2) * 16;
    const int cb = (w & 3) * 32;

    for (int tile = blockIdx.x; tile < numTiles; tile += gridDim.x) {
        const int base = tile * 64;

        #pragma unroll
        for (int rr = 0; rr < 4; rr++) {
            int row = w * 4 + rr, node = base + row;
            uint4 o = make_uint4(0u, 0u, 0u, 0u);
            if (node < N) {
                float4 v = *(const float4*)(ent + (size_t)node * 128 + lane * 4);
                float ss = v.x * v.x + v.y * v.y + v.z * v.z + v.w * v.w;
                #pragma unroll
                for (int off = 16; off > 0; off >>= 1)
                    ss += __shfl_xor_sync(0xffffffffu, ss, off);
                float rn = 1.0f / fmaxf(sqrtf(ss), 1e-12f);
                o = make_uint4(f2tf(v.x * rn), f2tf(v.y * rn),
                               f2tf(v.z * rn), f2tf(v.w * rn));
            }
            *(uint4*)(hs + row * PAD + lane * 4) = o;
        }
        __syncthreads();

        float acc[4][4];
        #pragma unroll
        for (int nt = 0; nt < 4; nt++)
            #pragma unroll
            for (int i = 0; i < 4; i++) acc[nt][i] = 0.f;

        #pragma unroll
        for (int s = 0; s < 16; s++) {
            const int kb = s * 8;
            u32 a0 = hs[(rb + gid) * PAD + kb + t4];
            u32 a1 = hs[(rb + 8 + gid) * PAD + kb + t4];
            u32 a2 = hs[(rb + gid) * PAD + kb + t4 + 4];
            u32 a3 = hs[(rb + 8 + gid) * PAD + kb + t4 + 4];
            #pragma unroll
            for (int nt = 0; nt < 4; nt++) {
                int c0 = cb + nt * 8 + gid;
                u32 b0 = WT[c0 * PAD + kb + t4];
                u32 b1 = WT[c0 * PAD + kb + t4 + 4];
                mma8(acc[nt], a0, a1, a2, a3, b0, b1);
            }
        }

        #pragma unroll
        for (int nt = 0; nt < 4; nt++) {
            int rl = rb + gid;
            int c  = cb + nt * 8 + 2 * t4;
            int n0 = base + rl, n1 = base + rl + 8;
            if (n0 < N) *(float2*)(out + (size_t)n0 * 128 + c) =
                make_float2(acc[nt][0], acc[nt][1]);
            if (n1 < N) *(float2*)(out + (size_t)n1 * 128 + c) =
                make_float2(acc[nt][2], acc[nt][3]);
        }
        __syncthreads();
    }
}

// ---------------------------------------------------------------------------
// k_final: fused aggregation + gate.
// Load phase per row: acc = out[row] (h@Ws) + sum over dst-bucket edges of
// (hW[src]+relW[et])*norm; rrelu -> hs. Then gate MMA + sigmoid blend -> x.
// Persistent, 2 CTA/SM, 64-row tiles.
// ---------------------------------------------------------------------------
extern "C" __global__ void __launch_bounds__(512, 2)
k_final(float* __restrict__ x,
        const float* __restrict__ Wt,
        const float* __restrict__ bias,
        const float* __restrict__ his,
        int N, int numTiles)
{
    extern __shared__ float sm[];
    u32*   WT = (u32*)sm;          // [n][k] tf32
    float* hs = sm + 128 * PAD;    // [row][k] fp32 post-rrelu
    const int tid  = threadIdx.x;
    const int lane = tid & 31;
    const int w    = tid >> 5;
    const int gid  = lane >> 2;
    const int t4   = lane & 3;

    for (int idx = tid; idx < 128 * 128; idx += 512) {
        int k = idx >> 7, n = idx & 127;
        WT[n * PAD + k] = f2tf(Wt[idx]);
    }
    __syncthreads();

    const int rb = (w >> 2) * 16;
    const int cb = (w & 3) * 32;

    for (int tile = blockIdx.x; tile < numTiles; tile += gridDim.x) {
        const int base = tile * 64;

        // aggregate + rrelu: warp w handles rows 4w..4w+3
        #pragma unroll
        for (int rr = 0; rr < 4; rr++) {
            int row = w * 4 + rr, node = base + row;
            if (node < N) {
                float4 acc = *(const float4*)(x + (size_t)node * 128 + lane * 4);
                const int s0  = g_off[node];
                const int cnt = g_cnt[node];
                int i = 0;
                for (; i + 2 <= cnt; i += 2) {
                    uint2 r0 = g_rec[s0 + i];
                    uint2 r1 = g_rec[s0 + i + 1];
                    int sA = r0.x & 0x1FFFF, tA = r0.x >> 17;
                    int sB = r1.x & 0x1FFFF, tB = r1.x >> 17;
                    uint2 a0 = *(const uint2*)(g_hWh   + (size_t)sA * 64 + lane * 2);
                    uint2 b0 = *(const uint2*)(g_relWh + (size_t)tA * 64 + lane * 2);
                    uint2 a1 = *(const uint2*)(g_hWh   + (size_t)sB * 64 + lane * 2);
                    uint2 b1 = *(const uint2*)(g_relWh + (size_t)tB * 64 + lane * 2);
                    float n0 = __uint_as_float(r0.y);
                    float n1 = __uint_as_float(r1.y);
                    float2 ax = __half22float2(*(__half2*)&a0.x);
                    float2 ay = __half22float2(*(__half2*)&a0.y);
                    float2 bx = __half22float2(*(__half2*)&b0.x);
                    float2 by = __half22float2(*(__half2*)&b0.y);
                    acc.x += (ax.x + bx.x) * n0; acc.y += (ax.y + bx.y) * n0;
                    acc.z += (ay.x + by.x) * n0; acc.w += (ay.y + by.y) * n0;
                    ax = __half22float2(*(__half2*)&a1.x);
                    ay = __half22float2(*(__half2*)&a1.y);
                    bx = __half22float2(*(__half2*)&b1.x);
                    by = __half22float2(*(__half2*)&b1.y);
                    acc.x += (ax.x + bx.x) * n1; acc.y += (ax.y + bx.y) * n1;
                    acc.z += (ay.x + by.x) * n1; acc.w += (ay.y + by.y) * n1;
                }
                if (i < cnt) {
                    uint2 r = g_rec[s0 + i];
                    int sA = r.x & 0x1FFFF, tA = r.x >> 17;
                    uint2 a = *(const uint2*)(g_hWh   + (size_t)sA * 64 + lane * 2);
                    uint2 b = *(const uint2*)(g_relWh + (size_t)tA * 64 + lane * 2);
                    float n = __uint_as_float(r.y);
                    float2 ax = __half22float2(*(__half2*)&a.x);
                    float2 ay = __half22float2(*(__half2*)&a.y);
                    float2 bx = __half22float2(*(__half2*)&b.x);
                    float2 by = __half22float2(*(__half2*)&b.y);
                    acc.x += (ax.x + bx.x) * n; acc.y += (ax.y + bx.y) * n;
                    acc.z += (ay.x + by.x) * n; acc.w += (ay.y + by.y) * n;
                }
                acc.x = acc.x >= 0.f ? acc.x : RRELU_SLOPE * acc.x;
                acc.y = acc.y >= 0.f ? acc.y : RRELU_SLOPE * acc.y;
                acc.z = acc.z >= 0.f ? acc.z : RRELU_SLOPE * acc.z;
                acc.w = acc.w >= 0.f ? acc.w : RRELU_SLOPE * acc.w;
                *(float4*)(hs + row * PAD + lane * 4) = acc;
            } else {
                *(float4*)(hs + row * PAD + lane * 4) = make_float4(0.f, 0.f, 0.f, 0.f);
            }
        }
        __syncthreads();

        float acc[4][4];
        #pragma unroll
        for (int nt = 0; nt < 4; nt++)
            #pragma unroll
            for (int i = 0; i < 4; i++) acc[nt][i] = 0.f;

        #pragma unroll
        for (int s = 0; s < 16; s++) {
            const int kb = s * 8;
            u32 a0 = f2tf(hs[(rb + gid) * PAD + kb + t4]);
            u32 a1 = f2tf(hs[(rb + 8 + gid) * PAD + kb + t4]);
            u32 a2 = f2tf(hs[(rb + gid) * PAD + kb + t4 + 4]);
            u32 a3 = f2tf(hs[(rb + 8 + gid) * PAD + kb + t4 + 4]);
            #pragma unroll
            for (int nt = 0; nt < 4; nt++) {
                int c0 = cb + nt * 8 + gid;
                u32 b0 = WT[c0 * PAD + kb + t4];
                u32 b1 = WT[c0 * PAD + kb + t4 + 4];
                mma8(acc[nt], a0, a1, a2, a3, b0, b1);
            }
        }

        #pragma unroll
        for (int nt = 0; nt < 4; nt++) {
            int rl = rb + gid;
            int c  = cb + nt * 8 + 2 * t4;
            float2 bv = *(const float2*)(bias + c);
            #pragma unroll
            for (int half = 0; half < 2; half++) {
                int row  = rl + half * 8;
                int node = base + row;
                if (node >= N) continue;
                float l0 = acc[nt][half * 2 + 0] + bv.x;
                float l1 = acc[nt][half * 2 + 1] + bv.y;
                float s0 = 1.0f / (1.0f + __expf(-l0));
                float s1 = 1.0f / (1.0f + __expf(-l1));
                float2 hv = *(const float2*)(hs + row * PAD + c);
                float2 hh = *(const float2*)(his + (size_t)node * 128 + c);
                float2 o = make_float2(s0 * hv.x + (1.f - s0) * hh.x,
                                       s1 * hv.y + (1.f - s1) * hh.y);
                *(float2*)(x + (size_t)node * 128 + c) = o;
            }
        }
        __syncthreads();
    }
}

// ---------------------------------------------------------------------------
extern "C" void kernel_launch(void* const* d_in, const int* in_sizes, int n_in,
                              void* d_out, int out_size)
{
    const float* ent   = (const float*)d_in[0];
    const float* rel   = (const float*)d_in[1];
    const float* his   = (const float*)d_in[2];
    const float* Wn    = (const float*)d_in[3];
    const float* Ws    = (const float*)d_in[4];
    const float* Wt    = (const float*)d_in[5];
    const float* bias  = (const float*)d_in[6];
    const float* enorm = (const float*)d_in[7];
    const int*   src   = (const int*)d_in[8];
    const int*   dst   = (const int*)d_in[9];
    const int*   et    = (const int*)d_in[10];

    int N = in_sizes[0] / DHID;
    int R = in_sizes[1] / DHID;
    int E = in_sizes[7];
    float* out = (float*)d_out;

    int* cnt;
    cudaGetSymbolAddress((void**)&cnt, g_cnt);

    int dev = 0, sms = 148;
    cudaGetDevice(&dev);
    cudaDeviceGetAttribute(&sms, cudaDevAttrMultiProcessorCount, dev);

    const int numTiles  = (N + 63) / 64;
    const int numTilesG = (N + R + 63) / 64;
    const int nb        = (N + 1023) / 1024;
    const int smG = (128 * PAD + 64 * PAD) * sizeof(float);   // ~101.4 KB
    cudaFuncSetAttribute(k_gemm16, cudaFuncAttributeMaxDynamicSharedMemorySize, smG);
    cudaFuncSetAttribute(k_gemm32, cudaFuncAttributeMaxDynamicSharedMemorySize, smG);
    cudaFuncSetAttribute(k_final,  cudaFuncAttributeMaxDynamicSharedMemorySize, smG);

    // Edge counting sort by dst
    k_zero<<<nb, 1024>>>(cnt, N);
    k_hist<<<(E + 255) / 256, 256>>>(dst, E);
    k_scan1<<<nb, 1024>>>(N);
    k_scan2<<<1, 256>>>(nb);
    k_scan3<<<nb, 1024>>>(N);
    k_scatter<<<(E + 255) / 256, 256>>>(src, dst, et, enorm, E);

    // Node pipeline
    k_gemm16<<<2 * sms, 512, smG>>>(ent, rel, Wn, N, R, numTilesG);
    k_gemm32<<<2 * sms, 512, smG>>>(ent, Ws, out, N, numTiles);
    k_final<<<2 * sms, 512, smG>>>(out, Wt, bias, his, N, numTiles);
}

// round 9
// speedup vs baseline: 1.8940x; 1.0034x over previous
#include <cuda_runtime.h>
#include <cuda_fp16.h>
#include <cstdint>
#include <math.h>

#define DHID 128
#define MAX_ENTS 100000
#define MAX_RELS 1000
#define MAX_EDGES 2000000
#define RRELU_SLOPE 0.22916666666666666f
#define PAD 132

typedef uint32_t u32;

__device__ __half2 g_hWh[MAX_ENTS * 64];         // h@Wn fp16
__device__ __half2 g_relWh[MAX_RELS * 64];       // rel@Wn fp16
__device__ int     g_cnt[MAX_ENTS];              // per-dst edge counts
__device__ int     g_off[MAX_ENTS];              // bucket start offsets
__device__ int     g_cur[MAX_ENTS];              // scatter cursors
__device__ int     g_bsum[256];                  // scan partials
__device__ uint2   g_rec[MAX_EDGES];             // (src | et<<17, norm_bits)

__device__ __forceinline__ u32 f2tf(float x) {
    u32 r; asm("cvt.rna.tf32.f32 %0, %1;" : "=r"(r) : "f"(x)); return r;
}
__device__ __forceinline__ void mma8(float* c, u32 a0, u32 a1, u32 a2, u32 a3,
                                     u32 b0, u32 b1) {
    asm volatile(
        "mma.sync.aligned.m16n8k8.row.col.f32.tf32.tf32.f32 "
        "{%0,%1,%2,%3}, {%4,%5,%6,%7}, {%8,%9}, {%0,%1,%2,%3};"
        : "+f"(c[0]), "+f"(c[1]), "+f"(c[2]), "+f"(c[3])
        : "r"(a0), "r"(a1), "r"(a2), "r"(a3), "r"(b0), "r"(b1));
}

// ---------------------------------------------------------------------------
// Edge counting sort by dst (runs on side stream, overlapped with GEMMs)
// ---------------------------------------------------------------------------
extern "C" __global__ void k_zero(int* __restrict__ p, int n) {
    int i = blockIdx.x * 1024 + threadIdx.x;
    if (i < n) p[i] = 0;
}

extern "C" __global__ void __launch_bounds__(256)
k_hist(const int* __restrict__ dst, int E)
{
    int e = blockIdx.x * 256 + threadIdx.x;
    if (e < E) atomicAdd(&g_cnt[dst[e]], 1);
}

extern "C" __global__ void __launch_bounds__(1024)
k_scan1(int N)
{
    __shared__ int smi[1024];
    int i = blockIdx.x * 1024 + threadIdx.x;
    int v = (i < N) ? g_cnt[i] : 0;
    smi[threadIdx.x] = v;
    __syncthreads();
    for (int off = 512; off > 0; off >>= 1) {
        if (threadIdx.x < off) smi[threadIdx.x] += smi[threadIdx.x + off];
        __syncthreads();
    }
    if (threadIdx.x == 0) g_bsum[blockIdx.x] = smi[0];
}

extern "C" __global__ void __launch_bounds__(256)
k_scan2(int nb)
{
    __shared__ int s[256];
    int t = threadIdx.x;
    int v = (t < nb) ? g_bsum[t] : 0;
    s[t] = v;
    __syncthreads();
    #pragma unroll
    for (int off = 1; off < 256; off <<= 1) {
        int x = (t >= off) ? s[t - off] : 0;
        __syncthreads();
        s[t] += x;
        __syncthreads();
    }
    if (t < nb) g_bsum[t] = s[t] - v;   // exclusive
}

extern "C" __global__ void __launch_bounds__(1024)
k_scan3(int N)
{
    __shared__ int smi[1024];
    int i = blockIdx.x * 1024 + threadIdx.x;
    int v = (i < N) ? g_cnt[i] : 0;
    smi[threadIdx.x] = v;
    __syncthreads();
    #pragma unroll
    for (int off = 1; off < 1024; off <<= 1) {
        int x = (threadIdx.x >= off) ? smi[threadIdx.x - off] : 0;
        __syncthreads();
        smi[threadIdx.x] += x;
        __syncthreads();
    }
    if (i < N) {
        int ex = smi[threadIdx.x] - v + g_bsum[blockIdx.x];
        g_off[i] = ex;
        g_cur[i] = ex;
    }
}

extern "C" __global__ void __launch_bounds__(256)
k_scatter(const int* __restrict__ src, const int* __restrict__ dst,
          const int* __restrict__ et, const float* __restrict__ enorm, int E)
{
    int e = blockIdx.x * 256 + threadIdx.x;
    if (e >= E) return;
    int d   = dst[e];
    int pos = atomicAdd(&g_cur[d], 1);
    g_rec[pos] = make_uint2((u32)src[e] | ((u32)et[e] << 17),
                            __float_as_uint(enorm[e]));
}

// ---------------------------------------------------------------------------
// k_gemm16: fp16 out = normalize(ent) @ Wn rows [0,N); rel rows [N,N+R).
// Persistent, 2 CTA/SM. smem: WT[128][PAD] | hs[64][PAD] tf32.
// ---------------------------------------------------------------------------
extern "C" __global__ void __launch_bounds__(512, 2)
k_gemm16(const float* __restrict__ ent, const float* __restrict__ rel,
         const float* __restrict__ W, int N, int R, int numTiles)
{
    extern __shared__ u32 smu[];
    u32* WT = smu;               // [n][k] tf32
    u32* hs = smu + 128 * PAD;   // [row][k] tf32
    const int tid  = threadIdx.x;
    const int lane = tid & 31;
    const int w    = tid >> 5;
    const int gid  = lane >> 2;
    const int t4   = lane & 3;

    for (int idx = tid; idx < 128 * 128; idx += 512) {
        int k = idx >> 7, n = idx & 127;
        WT[n * PAD + k] = f2tf(W[idx]);
    }
    __syncthreads();

    const int rb = (w >> 2) * 16;
    const int cb = (w & 3) * 32;

    for (int tile = blockIdx.x; tile < numTiles; tile += gridDim.x) {
        const int base = tile * 64;

        #pragma unroll
        for (int rr = 0; rr < 4; rr++) {
            int row = w * 4 + rr, node = base + row;
            uint4 o = make_uint4(0u, 0u, 0u, 0u);
            if (node < N) {
                float4 v = *(const float4*)(ent + (size_t)node * 128 + lane * 4);
                float ss = v.x * v.x + v.y * v.y + v.z * v.z + v.w * v.w;
                #pragma unroll
                for (int off = 16; off > 0; off >>= 1)
                    ss += __shfl_xor_sync(0xffffffffu, ss, off);
                float rn = 1.0f / fmaxf(sqrtf(ss), 1e-12f);
                o = make_uint4(f2tf(v.x * rn), f2tf(v.y * rn),
                               f2tf(v.z * rn), f2tf(v.w * rn));
            } else if (node < N + R) {
                float4 v = *(const float4*)(rel + (size_t)(node - N) * 128 + lane * 4);
                o = make_uint4(f2tf(v.x), f2tf(v.y), f2tf(v.z), f2tf(v.w));
            }
            *(uint4*)(hs + row * PAD + lane * 4) = o;
        }
        __syncthreads();

        float acc[4][4];
        #pragma unroll
        for (int nt = 0; nt < 4; nt++)
            #pragma unroll
            for (int i = 0; i < 4; i++) acc[nt][i] = 0.f;

        #pragma unroll
        for (int s = 0; s < 16; s++) {
            const int kb = s * 8;
            u32 a0 = hs[(rb + gid) * PAD + kb + t4];
            u32 a1 = hs[(rb + 8 + gid) * PAD + kb + t4];
            u32 a2 = hs[(rb + gid) * PAD + kb + t4 + 4];
            u32 a3 = hs[(rb + 8 + gid) * PAD + kb + t4 + 4];
            #pragma unroll
            for (int nt = 0; nt < 4; nt++) {
                int c0 = cb + nt * 8 + gid;
                u32 b0 = WT[c0 * PAD + kb + t4];
                u32 b1 = WT[c0 * PAD + kb + t4 + 4];
                mma8(acc[nt], a0, a1, a2, a3, b0, b1);
            }
        }

        #pragma unroll
        for (int nt = 0; nt < 4; nt++) {
            int rl = rb + gid;
            int c  = cb + nt * 8 + 2 * t4;
            #pragma unroll
            for (int half = 0; half < 2; half++) {
                int node = base + rl + half * 8;
                __half2 p = __floats2half2_rn(acc[nt][half * 2], acc[nt][half * 2 + 1]);
                if (node < N)          g_hWh[(size_t)node * 64 + (c >> 1)] = p;
                else if (node < N + R) g_relWh[(size_t)(node - N) * 64 + (c >> 1)] = p;
            }
        }
        __syncthreads();
    }
}

// ---------------------------------------------------------------------------
// k_gemm32: d_out = normalize(ent) @ Ws. Persistent, 2 CTA/SM.
// ---------------------------------------------------------------------------
extern "C" __global__ void __launch_bounds__(512, 2)
k_gemm32(const float* __restrict__ ent, const float* __restrict__ W,
         float* __restrict__ out, int N, int numTiles)
{
    extern __shared__ u32 smu[];
    u32* WT = smu;
    u32* hs = smu + 128 * PAD;
    const int tid  = threadIdx.x;
    const int lane = tid & 31;
    const int w    = tid >> 5;
    const int gid  = lane >> 2;
    const int t4   = lane & 3;

    for (int idx = tid; idx < 128 * 128; idx += 512) {
        int k = idx >> 7, n = idx & 127;
        WT[n * PAD + k] = f2tf(W[idx]);
    }
    __syncthreads();

    const int rb = (w >> 2) * 16;
    const int cb = (w & 3) * 32;

    for (int tile = blockIdx.x; tile < numTiles; tile += gridDim.x) {
        const int base = tile * 64;

        #pragma unroll
        for (int rr = 0; rr < 4; rr++) {
            int row = w * 4 + rr, node = base + row;
            uint4 o = make_uint4(0u, 0u, 0u, 0u);
            if (node < N) {
                float4 v = *(const float4*)(ent + (size_t)node * 128 + lane * 4);
                float ss = v.x * v.x + v.y * v.y + v.z * v.z + v.w * v.w;
                #pragma unroll
                for (int off = 16; off > 0; off >>= 1)
                    ss += __shfl_xor_sync(0xffffffffu, ss, off);
                float rn = 1.0f / fmaxf(sqrtf(ss), 1e-12f);
                o = make_uint4(f2tf(v.x * rn), f2tf(v.y * rn),
                               f2tf(v.z * rn), f2tf(v.w * rn));
            }
            *(uint4*)(hs + row * PAD + lane * 4) = o;
        }
        __syncthreads();

        float acc[4][4];
        #pragma unroll
        for (int nt = 0; nt < 4; nt++)
            #pragma unroll
            for (int i = 0; i < 4; i++) acc[nt][i] = 0.f;

        #pragma unroll
        for (int s = 0; s < 16; s++) {
            const int kb = s * 8;
            u32 a0 = hs[(rb + gid) * PAD + kb + t4];
            u32 a1 = hs[(rb + 8 + gid) * PAD + kb + t4];
            u32 a2 = hs[(rb + gid) * PAD + kb + t4 + 4];
            u32 a3 = hs[(rb + 8 + gid) * PAD + kb + t4 + 4];
            #pragma unroll
            for (int nt = 0; nt < 4; nt++) {
                int c0 = cb + nt * 8 + gid;
                u32 b0 = WT[c0 * PAD + kb + t4];
                u32 b1 = WT[c0 * PAD + kb + t4 + 4];
                mma8(acc[nt], a0, a1, a2, a3, b0, b1);
            }
        }

        #pragma unroll
        for (int nt = 0; nt < 4; nt++) {
            int rl = rb + gid;
            int c  = cb + nt * 8 + 2 * t4;
            int n0 = base + rl, n1 = base + rl + 8;
            if (n0 < N) *(float2*)(out + (size_t)n0 * 128 + c) =
                make_float2(acc[nt][0], acc[nt][1]);
            if (n1 < N) *(float2*)(out + (size_t)n1 * 128 + c) =
                make_float2(acc[nt][2], acc[nt][3]);
        }
        __syncthreads();
    }
}

// ---------------------------------------------------------------------------
// k_final: fused aggregation + gate. Persistent, 2 CTA/SM, 64-row tiles.
// ---------------------------------------------------------------------------
extern "C" __global__ void __launch_bounds__(512, 2)
k_final(float* __restrict__ x,
        const float* __restrict__ Wt,
        const float* __restrict__ bias,
        const float* __restrict__ his,
        int N, int numTiles)
{
    extern __shared__ float sm[];
    u32*   WT = (u32*)sm;          // [n][k] tf32
    float* hs = sm + 128 * PAD;    // [row][k] fp32 post-rrelu
    const int tid  = threadIdx.x;
    const int lane = tid & 31;
    const int w    = tid >> 5;
    const int gid  = lane >> 2;
    const int t4   = lane & 3;

    for (int idx = tid; idx < 128 * 128; idx += 512) {
        int k = idx >> 7, n = idx & 127;
        WT[n * PAD + k] = f2tf(Wt[idx]);
    }
    __syncthreads();

    const int rb = (w >> 2) * 16;
    const int cb = (w & 3) * 32;

    for (int tile = blockIdx.x; tile < numTiles; tile += gridDim.x) {
        const int base = tile * 64;

        #pragma unroll
        for (int rr = 0; rr < 4; rr++) {
            int row = w * 4 + rr, node = base + row;
            if (node < N) {
                float4 acc = *(const float4*)(x + (size_t)node * 128 + lane * 4);
                const int s0  = g_off[node];
                const int cnt = g_cnt[node];
                int i = 0;
                for (; i + 2 <= cnt; i += 2) {
                    uint2 r0 = g_rec[s0 + i];
                    uint2 r1 = g_rec[s0 + i + 1];
                    int sA = r0.x & 0x1FFFF, tA = r0.x >> 17;
                    int sB = r1.x & 0x1FFFF, tB = r1.x >> 17;
                    uint2 a0 = *(const uint2*)(g_hWh   + (size_t)sA * 64 + lane * 2);
                    uint2 b0 = *(const uint2*)(g_relWh + (size_t)tA * 64 + lane * 2);
                    uint2 a1 = *(const uint2*)(g_hWh   + (size_t)sB * 64 + lane * 2);
                    uint2 b1 = *(const uint2*)(g_relWh + (size_t)tB * 64 + lane * 2);
                    float n0 = __uint_as_float(r0.y);
                    float n1 = __uint_as_float(r1.y);
                    float2 ax = __half22float2(*(__half2*)&a0.x);
                    float2 ay = __half22float2(*(__half2*)&a0.y);
                    float2 bx = __half22float2(*(__half2*)&b0.x);
                    float2 by = __half22float2(*(__half2*)&b0.y);
                    acc.x += (ax.x + bx.x) * n0; acc.y += (ax.y + bx.y) * n0;
                    acc.z += (ay.x + by.x) * n0; acc.w += (ay.y + by.y) * n0;
                    ax = __half22float2(*(__half2*)&a1.x);
                    ay = __half22float2(*(__half2*)&a1.y);
                    bx = __half22float2(*(__half2*)&b1.x);
                    by = __half22float2(*(__half2*)&b1.y);
                    acc.x += (ax.x + bx.x) * n1; acc.y += (ax.y + bx.y) * n1;
                    acc.z += (ay.x + by.x) * n1; acc.w += (ay.y + by.y) * n1;
                }
                if (i < cnt) {
                    uint2 r = g_rec[s0 + i];
                    int sA = r.x & 0x1FFFF, tA = r.x >> 17;
                    uint2 a = *(const uint2*)(g_hWh   + (size_t)sA * 64 + lane * 2);
                    uint2 b = *(const uint2*)(g_relWh + (size_t)tA * 64 + lane * 2);
                    float n = __uint_as_float(r.y);
                    float2 ax = __half22float2(*(__half2*)&a.x);
                    float2 ay = __half22float2(*(__half2*)&a.y);
                    float2 bx = __half22float2(*(__half2*)&b.x);
                    float2 by = __half22float2(*(__half2*)&b.y);
                    acc.x += (ax.x + bx.x) * n; acc.y += (ax.y + bx.y) * n;
                    acc.z += (ay.x + by.x) * n; acc.w += (ay.y + by.y) * n;
                }
                acc.x = acc.x >= 0.f ? acc.x : RRELU_SLOPE * acc.x;
                acc.y = acc.y >= 0.f ? acc.y : RRELU_SLOPE * acc.y;
                acc.z = acc.z >= 0.f ? acc.z : RRELU_SLOPE * acc.z;
                acc.w = acc.w >= 0.f ? acc.w : RRELU_SLOPE * acc.w;
                *(float4*)(hs + row * PAD + lane * 4) = acc;
            } else {
                *(float4*)(hs + row * PAD + lane * 4) = make_float4(0.f, 0.f, 0.f, 0.f);
            }
        }
        __syncthreads();

        float acc[4][4];
        #pragma unroll
        for (int nt = 0; nt < 4; nt++)
            #pragma unroll
            for (int i = 0; i < 4; i++) acc[nt][i] = 0.f;

        #pragma unroll
        for (int s = 0; s < 16; s++) {
            const int kb = s * 8;
            u32 a0 = f2tf(hs[(rb + gid) * PAD + kb + t4]);
            u32 a1 = f2tf(hs[(rb + 8 + gid) * PAD + kb + t4]);
            u32 a2 = f2tf(hs[(rb + gid) * PAD + kb + t4 + 4]);
            u32 a3 = f2tf(hs[(rb + 8 + gid) * PAD + kb + t4 + 4]);
            #pragma unroll
            for (int nt = 0; nt < 4; nt++) {
                int c0 = cb + nt * 8 + gid;
                u32 b0 = WT[c0 * PAD + kb + t4];
                u32 b1 = WT[c0 * PAD + kb + t4 + 4];
                mma8(acc[nt], a0, a1, a2, a3, b0, b1);
            }
        }

        #pragma unroll
        for (int nt = 0; nt < 4; nt++) {
            int rl = rb + gid;
            int c  = cb + nt * 8 + 2 * t4;
            float2 bv = *(const float2*)(bias + c);
            #pragma unroll
            for (int half = 0; half < 2; half++) {
                int row  = rl + half * 8;
                int node = base + row;
                if (node >= N) continue;
                float l0 = acc[nt][half * 2 + 0] + bv.x;
                float l1 = acc[nt][half * 2 + 1] + bv.y;
                float s0 = 1.0f / (1.0f + __expf(-l0));
                float s1 = 1.0f / (1.0f + __expf(-l1));
                float2 hv = *(const float2*)(hs + row * PAD + c);
                float2 hh = *(const float2*)(his + (size_t)node * 128 + c);
                float2 o = make_float2(s0 * hv.x + (1.f - s0) * hh.x,
                                       s1 * hv.y + (1.f - s1) * hh.y);
                *(float2*)(x + (size_t)node * 128 + c) = o;
            }
        }
        __syncthreads();
    }
}

// ---------------------------------------------------------------------------
extern "C" void kernel_launch(void* const* d_in, const int* in_sizes, int n_in,
                              void* d_out, int out_size)
{
    const float* ent   = (const float*)d_in[0];
    const float* rel   = (const float*)d_in[1];
    const float* his   = (const float*)d_in[2];
    const float* Wn    = (const float*)d_in[3];
    const float* Ws    = (const float*)d_in[4];
    const float* Wt    = (const float*)d_in[5];
    const float* bias  = (const float*)d_in[6];
    const float* enorm = (const float*)d_in[7];
    const int*   src   = (const int*)d_in[8];
    const int*   dst   = (const int*)d_in[9];
    const int*   et    = (const int*)d_in[10];

    int N = in_sizes[0] / DHID;
    int R = in_sizes[1] / DHID;
    int E = in_sizes[7];
    float* out = (float*)d_out;

    int* cnt;
    cudaGetSymbolAddress((void**)&cnt, g_cnt);

    int dev = 0, sms = 148;
    cudaGetDevice(&dev);
    cudaDeviceGetAttribute(&sms, cudaDevAttrMultiProcessorCount, dev);

    const int numTiles  = (N + 63) / 64;
    const int numTilesG = (N + R + 63) / 64;
    const int nb        = (N + 1023) / 1024;
    const int smG = (128 * PAD + 64 * PAD) * sizeof(float);   // ~101.4 KB
    cudaFuncSetAttribute(k_gemm16, cudaFuncAttributeMaxDynamicSharedMemorySize, smG);
    cudaFuncSetAttribute(k_gemm32, cudaFuncAttributeMaxDynamicSharedMemorySize, smG);
    cudaFuncSetAttribute(k_final,  cudaFuncAttributeMaxDynamicSharedMemorySize, smG);

    // Lazily created host-side objects (first call is the uncaptured
    // correctness run, so creation happens outside graph capture).
    static cudaStream_t s_side = nullptr;
    static cudaEvent_t  ev_fork = nullptr, ev_join = nullptr;
    if (s_side == nullptr) {
        cudaStreamCreateWithFlags(&s_side, cudaStreamNonBlocking);
        cudaEventCreateWithFlags(&ev_fork, cudaEventDisableTiming);
        cudaEventCreateWithFlags(&ev_join, cudaEventDisableTiming);
    }

    // ---- fork: edge counting-sort chain on side stream -------------------
    cudaEventRecord(ev_fork, 0);
    cudaStreamWaitEvent(s_side, ev_fork, 0);
    k_zero<<<nb, 1024, 0, s_side>>>(cnt, N);
    k_hist<<<(E + 255) / 256, 256, 0, s_side>>>(dst, E);
    k_scan1<<<nb, 1024, 0, s_side>>>(N);
    k_scan2<<<1, 256, 0, s_side>>>(nb);
    k_scan3<<<nb, 1024, 0, s_side>>>(N);
    k_scatter<<<(E + 255) / 256, 256, 0, s_side>>>(src, dst, et, enorm, E);
    cudaEventRecord(ev_join, s_side);

    // ---- main stream: node GEMMs (overlapped with the sort) --------------
    k_gemm16<<<2 * sms, 512, smG>>>(ent, rel, Wn, N, R, numTilesG);
    k_gemm32<<<2 * sms, 512, smG>>>(ent, Ws, out, N, numTiles);

    // ---- join, then fused aggregate + gate -------------------------------
    cudaStreamWaitEvent(0, ev_join, 0);
    k_final<<<2 * sms, 512, smG>>>(out, Wt, bias, his, N, numTiles);
}

// round 10
// speedup vs baseline: 1.9823x; 1.0466x over previous
#include <cuda_runtime.h>
#include <cuda_fp16.h>
#include <cstdint>
#include <math.h>

#define DHID 128
#define MAX_ENTS 100000
#define MAX_RELS 1000
#define MAX_EDGES 2000000
#define RRELU_SLOPE 0.22916666666666666f
#define PAD 132

typedef uint32_t u32;

__device__ __half2 g_hWh[MAX_ENTS * 64];         // h@Wn fp16
__device__ __half2 g_relWh[MAX_RELS * 64];       // rel@Wn fp16
__device__ int     g_cnt[MAX_ENTS];              // per-dst edge counts
__device__ int     g_off[MAX_ENTS];              // bucket start offsets
__device__ int     g_cur[MAX_ENTS];              // scatter cursors
__device__ int     g_bsum[256];                  // scan partials
__device__ uint2   g_rec[MAX_EDGES];             // (src | et<<17, norm_bits)

__device__ __forceinline__ u32 f2tf(float x) {
    u32 r; asm("cvt.rna.tf32.f32 %0, %1;" : "=r"(r) : "f"(x)); return r;
}
__device__ __forceinline__ void mma8(float* c, u32 a0, u32 a1, u32 a2, u32 a3,
                                     u32 b0, u32 b1) {
    asm volatile(
        "mma.sync.aligned.m16n8k8.row.col.f32.tf32.tf32.f32 "
        "{%0,%1,%2,%3}, {%4,%5,%6,%7}, {%8,%9}, {%0,%1,%2,%3};"
        : "+f"(c[0]), "+f"(c[1]), "+f"(c[2]), "+f"(c[3])
        : "r"(a0), "r"(a1), "r"(a2), "r"(a3), "r"(b0), "r"(b1));
}

// ---------------------------------------------------------------------------
// Edge counting sort by dst (side stream, overlapped with GEMMs)
// ---------------------------------------------------------------------------
extern "C" __global__ void k_zero(int* __restrict__ p, int n) {
    int i = blockIdx.x * 1024 + threadIdx.x;
    if (i < n) p[i] = 0;
}

extern "C" __global__ void __launch_bounds__(256)
k_hist(const int* __restrict__ dst, int E)
{
    int e = blockIdx.x * 256 + threadIdx.x;
    if (e < E) atomicAdd(&g_cnt[dst[e]], 1);
}

extern "C" __global__ void __launch_bounds__(1024)
k_scan1(int N)
{
    __shared__ int smi[1024];
    int i = blockIdx.x * 1024 + threadIdx.x;
    int v = (i < N) ? g_cnt[i] : 0;
    smi[threadIdx.x] = v;
    __syncthreads();
    for (int off = 512; off > 0; off >>= 1) {
        if (threadIdx.x < off) smi[threadIdx.x] += smi[threadIdx.x + off];
        __syncthreads();
    }
    if (threadIdx.x == 0) g_bsum[blockIdx.x] = smi[0];
}

extern "C" __global__ void __launch_bounds__(256)
k_scan2(int nb)
{
    __shared__ int s[256];
    int t = threadIdx.x;
    int v = (t < nb) ? g_bsum[t] : 0;
    s[t] = v;
    __syncthreads();
    #pragma unroll
    for (int off = 1; off < 256; off <<= 1) {
        int x = (t >= off) ? s[t - off] : 0;
        __syncthreads();
        s[t] += x;
        __syncthreads();
    }
    if (t < nb) g_bsum[t] = s[t] - v;   // exclusive
}

extern "C" __global__ void __launch_bounds__(1024)
k_scan3(int N)
{
    __shared__ int smi[1024];
    int i = blockIdx.x * 1024 + threadIdx.x;
    int v = (i < N) ? g_cnt[i] : 0;
    smi[threadIdx.x] = v;
    __syncthreads();
    #pragma unroll
    for (int off = 1; off < 1024; off <<= 1) {
        int x = (threadIdx.x >= off) ? smi[threadIdx.x - off] : 0;
        __syncthreads();
        smi[threadIdx.x] += x;
        __syncthreads();
    }
    if (i < N) {
        int ex = smi[threadIdx.x] - v + g_bsum[blockIdx.x];
        g_off[i] = ex;
        g_cur[i] = ex;
    }
}

extern "C" __global__ void __launch_bounds__(256)
k_scatter(const int* __restrict__ src, const int* __restrict__ dst,
          const int* __restrict__ et, const float* __restrict__ enorm, int E)
{
    int e = blockIdx.x * 256 + threadIdx.x;
    if (e >= E) return;
    int d   = dst[e];
    int pos = atomicAdd(&g_cur[d], 1);
    g_rec[pos] = make_uint2((u32)src[e] | ((u32)et[e] << 17),
                            __float_as_uint(enorm[e]));
}

// ---------------------------------------------------------------------------
// k_gemm16: fp16 out = normalize(ent) @ Wn rows [0,N); rel rows [N,N+R).
// Persistent, 2 CTA/SM. smem: WT[128][PAD] | hs[64][PAD] tf32.
// ---------------------------------------------------------------------------
extern "C" __global__ void __launch_bounds__(512, 2)
k_gemm16(const float* __restrict__ ent, const float* __restrict__ rel,
         const float* __restrict__ W, int N, int R, int numTiles)
{
    extern __shared__ u32 smu[];
    u32* WT = smu;               // [n][k] tf32
    u32* hs = smu + 128 * PAD;   // [row][k] tf32
    const int tid  = threadIdx.x;
    const int lane = tid & 31;
    const int w    = tid >> 5;
    const int gid  = lane >> 2;
    const int t4   = lane & 3;

    for (int idx = tid; idx < 128 * 128; idx += 512) {
        int k = idx >> 7, n = idx & 127;
        WT[n * PAD + k] = f2tf(W[idx]);
    }
    __syncthreads();

    const int rb = (w >> 2) * 16;
    const int cb = (w & 3) * 32;

    for (int tile = blockIdx.x; tile < numTiles; tile += gridDim.x) {
        const int base = tile * 64;

        #pragma unroll
        for (int rr = 0; rr < 4; rr++) {
            int row = w * 4 + rr, node = base + row;
            uint4 o = make_uint4(0u, 0u, 0u, 0u);
            if (node < N) {
                float4 v = *(const float4*)(ent + (size_t)node * 128 + lane * 4);
                float ss = v.x * v.x + v.y * v.y + v.z * v.z + v.w * v.w;
                #pragma unroll
                for (int off = 16; off > 0; off >>= 1)
                    ss += __shfl_xor_sync(0xffffffffu, ss, off);
                float rn = 1.0f / fmaxf(sqrtf(ss), 1e-12f);
                o = make_uint4(f2tf(v.x * rn), f2tf(v.y * rn),
                               f2tf(v.z * rn), f2tf(v.w * rn));
            } else if (node < N + R) {
                float4 v = *(const float4*)(rel + (size_t)(node - N) * 128 + lane * 4);
                o = make_uint4(f2tf(v.x), f2tf(v.y), f2tf(v.z), f2tf(v.w));
            }
            *(uint4*)(hs + row * PAD + lane * 4) = o;
        }
        __syncthreads();

        float acc[4][4];
        #pragma unroll
        for (int nt = 0; nt < 4; nt++)
            #pragma unroll
            for (int i = 0; i < 4; i++) acc[nt][i] = 0.f;

        #pragma unroll
        for (int s = 0; s < 16; s++) {
            const int kb = s * 8;
            u32 a0 = hs[(rb + gid) * PAD + kb + t4];
            u32 a1 = hs[(rb + 8 + gid) * PAD + kb + t4];
            u32 a2 = hs[(rb + gid) * PAD + kb + t4 + 4];
            u32 a3 = hs[(rb + 8 + gid) * PAD + kb + t4 + 4];
            #pragma unroll
            for (int nt = 0; nt < 4; nt++) {
                int c0 = cb + nt * 8 + gid;
                u32 b0 = WT[c0 * PAD + kb + t4];
                u32 b1 = WT[c0 * PAD + kb + t4 + 4];
                mma8(acc[nt], a0, a1, a2, a3, b0, b1);
            }
        }

        #pragma unroll
        for (int nt = 0; nt < 4; nt++) {
            int rl = rb + gid;
            int c  = cb + nt * 8 + 2 * t4;
            #pragma unroll
            for (int half = 0; half < 2; half++) {
                int node = base + rl + half * 8;
                __half2 p = __floats2half2_rn(acc[nt][half * 2], acc[nt][half * 2 + 1]);
                if (node < N)          g_hWh[(size_t)node * 64 + (c >> 1)] = p;
                else if (node < N + R) g_relWh[(size_t)(node - N) * 64 + (c >> 1)] = p;
            }
        }
        __syncthreads();
    }
}

// ---------------------------------------------------------------------------
// k_gemm32: d_out = normalize(ent) @ Ws. Persistent, 2 CTA/SM.
// ---------------------------------------------------------------------------
extern "C" __global__ void __launch_bounds__(512, 2)
k_gemm32(const float* __restrict__ ent, const float* __restrict__ W,
         float* __restrict__ out, int N, int numTiles)
{
    extern __shared__ u32 smu[];
    u32* WT = smu;
    u32* hs = smu + 128 * PAD;
    const int tid  = threadIdx.x;
    const int lane = tid & 31;
    const int w    = tid >> 5;
    const int gid  = lane >> 2;
    const int t4   = lane & 3;

    for (int idx = tid; idx < 128 * 128; idx += 512) {
        int k = idx >> 7, n = idx & 127;
        WT[n * PAD + k] = f2tf(W[idx]);
    }
    __syncthreads();

    const int rb = (w >> 2) * 16;
    const int cb = (w & 3) * 32;

    for (int tile = blockIdx.x; tile < numTiles; tile += gridDim.x) {
        const int base = tile * 64;

        #pragma unroll
        for (int rr = 0; rr < 4; rr++) {
            int row = w * 4 + rr, node = base + row;
            uint4 o = make_uint4(0u, 0u, 0u, 0u);
            if (node < N) {
                float4 v = *(const float4*)(ent + (size_t)node * 128 + lane * 4);
                float ss = v.x * v.x + v.y * v.y + v.z * v.z + v.w * v.w;
                #pragma unroll
                for (int off = 16; off > 0; off >>= 1)
                    ss += __shfl_xor_sync(0xffffffffu, ss, off);
                float rn = 1.0f / fmaxf(sqrtf(ss), 1e-12f);
                o = make_uint4(f2tf(v.x * rn), f2tf(v.y * rn),
                               f2tf(v.z * rn), f2tf(v.w * rn));
            }
            *(uint4*)(hs + row * PAD + lane * 4) = o;
        }
        __syncthreads();

        float acc[4][4];
        #pragma unroll
        for (int nt = 0; nt < 4; nt++)
            #pragma unroll
            for (int i = 0; i < 4; i++) acc[nt][i] = 0.f;

        #pragma unroll
        for (int s = 0; s < 16; s++) {
            const int kb = s * 8;
            u32 a0 = hs[(rb + gid) * PAD + kb + t4];
            u32 a1 = hs[(rb + 8 + gid) * PAD + kb + t4];
            u32 a2 = hs[(rb + gid) * PAD + kb + t4 + 4];
            u32 a3 = hs[(rb + 8 + gid) * PAD + kb + t4 + 4];
            #pragma unroll
            for (int nt = 0; nt < 4; nt++) {
                int c0 = cb + nt * 8 + gid;
                u32 b0 = WT[c0 * PAD + kb + t4];
                u32 b1 = WT[c0 * PAD + kb + t4 + 4];
                mma8(acc[nt], a0, a1, a2, a3, b0, b1);
            }
        }

        #pragma unroll
        for (int nt = 0; nt < 4; nt++) {
            int rl = rb + gid;
            int c  = cb + nt * 8 + 2 * t4;
            int n0 = base + rl, n1 = base + rl + 8;
            if (n0 < N) *(float2*)(out + (size_t)n0 * 128 + c) =
                make_float2(acc[nt][0], acc[nt][1]);
            if (n1 < N) *(float2*)(out + (size_t)n1 * 128 + c) =
                make_float2(acc[nt][2], acc[nt][3]);
        }
        __syncthreads();
    }
}

// ---------------------------------------------------------------------------
// k_agg2: warp per dst, NO smem (full L1 carveout -> relW table L1-resident).
// acc = x[d] (h@Ws) + sum (hW[src]+relW[et])*norm over sorted bucket;
// rrelu fused; h_cur written back in place. 4-edge unroll for MLP.
// ---------------------------------------------------------------------------
extern "C" __global__ void __launch_bounds__(256)
k_agg2(float* __restrict__ x, int N)
{
    int d = blockIdx.x * 8 + (threadIdx.x >> 5);
    if (d >= N) return;
    int lane = threadIdx.x & 31;

    float4 acc = *(const float4*)(x + (size_t)d * 128 + lane * 4);
    const int s0  = g_off[d];
    const int cnt = g_cnt[d];

    int i = 0;
    for (; i + 4 <= cnt; i += 4) {
        uint2 r0 = __ldg(&g_rec[s0 + i]);
        uint2 r1 = __ldg(&g_rec[s0 + i + 1]);
        uint2 r2 = __ldg(&g_rec[s0 + i + 2]);
        uint2 r3 = __ldg(&g_rec[s0 + i + 3]);
        uint2 a0 = *(const uint2*)(g_hWh   + (size_t)(r0.x & 0x1FFFF) * 64 + lane * 2);
        uint2 a1 = *(const uint2*)(g_hWh   + (size_t)(r1.x & 0x1FFFF) * 64 + lane * 2);
        uint2 a2 = *(const uint2*)(g_hWh   + (size_t)(r2.x & 0x1FFFF) * 64 + lane * 2);
        uint2 a3 = *(const uint2*)(g_hWh   + (size_t)(r3.x & 0x1FFFF) * 64 + lane * 2);
        uint2 b0 = *(const uint2*)(g_relWh + (size_t)(r0.x >> 17) * 64 + lane * 2);
        uint2 b1 = *(const uint2*)(g_relWh + (size_t)(r1.x >> 17) * 64 + lane * 2);
        uint2 b2 = *(const uint2*)(g_relWh + (size_t)(r2.x >> 17) * 64 + lane * 2);
        uint2 b3 = *(const uint2*)(g_relWh + (size_t)(r3.x >> 17) * 64 + lane * 2);
        float n0 = __uint_as_float(r0.y), n1 = __uint_as_float(r1.y);
        float n2 = __uint_as_float(r2.y), n3 = __uint_as_float(r3.y);

        float2 axl, axh, bxl, bxh;
        axl = __half22float2(*(__half2*)&a0.x); axh = __half22float2(*(__half2*)&a0.y);
        bxl = __half22float2(*(__half2*)&b0.x); bxh = __half22float2(*(__half2*)&b0.y);
        acc.x += (axl.x + bxl.x) * n0; acc.y += (axl.y + bxl.y) * n0;
        acc.z += (axh.x + bxh.x) * n0; acc.w += (axh.y + bxh.y) * n0;
        axl = __half22float2(*(__half2*)&a1.x); axh = __half22float2(*(__half2*)&a1.y);
        bxl = __half22float2(*(__half2*)&b1.x); bxh = __half22float2(*(__half2*)&b1.y);
        acc.x += (axl.x + bxl.x) * n1; acc.y += (axl.y + bxl.y) * n1;
        acc.z += (axh.x + bxh.x) * n1; acc.w += (axh.y + bxh.y) * n1;
        axl = __half22float2(*(__half2*)&a2.x); axh = __half22float2(*(__half2*)&a2.y);
        bxl = __half22float2(*(__half2*)&b2.x); bxh = __half22float2(*(__half2*)&b2.y);
        acc.x += (axl.x + bxl.x) * n2; acc.y += (axl.y + bxl.y) * n2;
        acc.z += (axh.x + bxh.x) * n2; acc.w += (axh.y + bxh.y) * n2;
        axl = __half22float2(*(__half2*)&a3.x); axh = __half22float2(*(__half2*)&a3.y);
        bxl = __half22float2(*(__half2*)&b3.x); bxh = __half22float2(*(__half2*)&b3.y);
        acc.x += (axl.x + bxl.x) * n3; acc.y += (axl.y + bxl.y) * n3;
        acc.z += (axh.x + bxh.x) * n3; acc.w += (axh.y + bxh.y) * n3;
    }
    for (; i < cnt; i++) {
        uint2 r = __ldg(&g_rec[s0 + i]);
        uint2 a = *(const uint2*)(g_hWh   + (size_t)(r.x & 0x1FFFF) * 64 + lane * 2);
        uint2 b = *(const uint2*)(g_relWh + (size_t)(r.x >> 17) * 64 + lane * 2);
        float n = __uint_as_float(r.y);
        float2 axl = __half22float2(*(__half2*)&a.x);
        float2 axh = __half22float2(*(__half2*)&a.y);
        float2 bxl = __half22float2(*(__half2*)&b.x);
        float2 bxh = __half22float2(*(__half2*)&b.y);
        acc.x += (axl.x + bxl.x) * n; acc.y += (axl.y + bxl.y) * n;
        acc.z += (axh.x + bxh.x) * n; acc.w += (axh.y + bxh.y) * n;
    }

    acc.x = acc.x >= 0.f ? acc.x : RRELU_SLOPE * acc.x;
    acc.y = acc.y >= 0.f ? acc.y : RRELU_SLOPE * acc.y;
    acc.z = acc.z >= 0.f ? acc.z : RRELU_SLOPE * acc.z;
    acc.w = acc.w >= 0.f ? acc.w : RRELU_SLOPE * acc.w;
    *(float4*)(x + (size_t)d * 128 + lane * 4) = acc;
}

// ---------------------------------------------------------------------------
// k_final: gate only. x holds h_cur (post-rrelu). gate = sigmoid(h_cur@Wt+b);
// x = gate*h_cur + (1-gate)*his. Persistent, 2 CTA/SM, 64-row tiles.
// ---------------------------------------------------------------------------
extern "C" __global__ void __launch_bounds__(512, 2)
k_final(float* __restrict__ x,
        const float* __restrict__ Wt,
        const float* __restrict__ bias,
        const float* __restrict__ his,
        int N, int numTiles)
{
    extern __shared__ float sm[];
    u32*   WT = (u32*)sm;          // [n][k] tf32
    float* hs = sm + 128 * PAD;    // [row][k] fp32 h_cur
    const int tid  = threadIdx.x;
    const int lane = tid & 31;
    const int w    = tid >> 5;
    const int gid  = lane >> 2;
    const int t4   = lane & 3;

    for (int idx = tid; idx < 128 * 128; idx += 512) {
        int k = idx >> 7, n = idx & 127;
        WT[n * PAD + k] = f2tf(Wt[idx]);
    }
    __syncthreads();

    const int rb = (w >> 2) * 16;
    const int cb = (w & 3) * 32;

    for (int tile = blockIdx.x; tile < numTiles; tile += gridDim.x) {
        const int base = tile * 64;

        for (int i = tid; i < 64 * 32; i += 512) {
            int row = i >> 5, kq = i & 31, node = base + row;
            float4 v = make_float4(0.f, 0.f, 0.f, 0.f);
            if (node < N) v = *(const float4*)(x + (size_t)node * 128 + kq * 4);
            *(float4*)(hs + row * PAD + kq * 4) = v;
        }
        __syncthreads();

        float acc[4][4];
        #pragma unroll
        for (int nt = 0; nt < 4; nt++)
            #pragma unroll
            for (int i = 0; i < 4; i++) acc[nt][i] = 0.f;

        #pragma unroll
        for (int s = 0; s < 16; s++) {
            const int kb = s * 8;
            u32 a0 = f2tf(hs[(rb + gid) * PAD + kb + t4]);
            u32 a1 = f2tf(hs[(rb + 8 + gid) * PAD + kb + t4]);
            u32 a2 = f2tf(hs[(rb + gid) * PAD + kb + t4 + 4]);
            u32 a3 = f2tf(hs[(rb + 8 + gid) * PAD + kb + t4 + 4]);
            #pragma unroll
            for (int nt = 0; nt < 4; nt++) {
                int c0 = cb + nt * 8 + gid;
                u32 b0 = WT[c0 * PAD + kb + t4];
                u32 b1 = WT[c0 * PAD + kb + t4 + 4];
                mma8(acc[nt], a0, a1, a2, a3, b0, b1);
            }
        }

        #pragma unroll
        for (int nt = 0; nt < 4; nt++) {
            int rl = rb + gid;
            int c  = cb + nt * 8 + 2 * t4;
            float2 bv = *(const float2*)(bias + c);
            #pragma unroll
            for (int half = 0; half < 2; half++) {
                int row  = rl + half * 8;
                int node = base + row;
                if (node >= N) continue;
                float l0 = acc[nt][half * 2 + 0] + bv.x;
                float l1 = acc[nt][half * 2 + 1] + bv.y;
                float s0 = 1.0f / (1.0f + __expf(-l0));
                float s1 = 1.0f / (1.0f + __expf(-l1));
                float2 hv = *(const float2*)(hs + row * PAD + c);
                float2 hh = *(const float2*)(his + (size_t)node * 128 + c);
                float2 o = make_float2(s0 * hv.x + (1.f - s0) * hh.x,
                                       s1 * hv.y + (1.f - s1) * hh.y);
                *(float2*)(x + (size_t)node * 128 + c) = o;
            }
        }
        __syncthreads();
    }
}

// ---------------------------------------------------------------------------
extern "C" void kernel_launch(void* const* d_in, const int* in_sizes, int n_in,
                              void* d_out, int out_size)
{
    const float* ent   = (const float*)d_in[0];
    const float* rel   = (const float*)d_in[1];
    const float* his   = (const float*)d_in[2];
    const float* Wn    = (const float*)d_in[3];
    const float* Ws    = (const float*)d_in[4];
    const float* Wt    = (const float*)d_in[5];
    const float* bias  = (const float*)d_in[6];
    const float* enorm = (const float*)d_in[7];
    const int*   src   = (const int*)d_in[8];
    const int*   dst   = (const int*)d_in[9];
    const int*   et    = (const int*)d_in[10];

    int N = in_sizes[0] / DHID;
    int R = in_sizes[1] / DHID;
    int E = in_sizes[7];
    float* out = (float*)d_out;

    int* cnt;
    cudaGetSymbolAddress((void**)&cnt, g_cnt);

    int dev = 0, sms = 148;
    cudaGetDevice(&dev);
    cudaDeviceGetAttribute(&sms, cudaDevAttrMultiProcessorCount, dev);

    const int numTiles  = (N + 63) / 64;
    const int numTilesG = (N + R + 63) / 64;
    const int nb        = (N + 1023) / 1024;
    const int smG = (128 * PAD + 64 * PAD) * sizeof(float);   // ~101.4 KB
    cudaFuncSetAttribute(k_gemm16, cudaFuncAttributeMaxDynamicSharedMemorySize, smG);
    cudaFuncSetAttribute(k_gemm32, cudaFuncAttributeMaxDynamicSharedMemorySize, smG);
    cudaFuncSetAttribute(k_final,  cudaFuncAttributeMaxDynamicSharedMemorySize, smG);
    // Max L1 carveout for the gather kernel (relW table L1-resident)
    cudaFuncSetAttribute(k_agg2, cudaFuncAttributePreferredSharedMemoryCarveout,
                         cudaSharedmemCarveoutMaxL1);

    static cudaStream_t s_side = nullptr;
    static cudaEvent_t  ev_fork = nullptr, ev_join = nullptr;
    if (s_side == nullptr) {
        cudaStreamCreateWithFlags(&s_side, cudaStreamNonBlocking);
        cudaEventCreateWithFlags(&ev_fork, cudaEventDisableTiming);
        cudaEventCreateWithFlags(&ev_join, cudaEventDisableTiming);
    }

    // ---- fork: edge counting-sort chain on side stream -------------------
    cudaEventRecord(ev_fork, 0);
    cudaStreamWaitEvent(s_side, ev_fork, 0);
    k_zero<<<nb, 1024, 0, s_side>>>(cnt, N);
    k_hist<<<(E + 255) / 256, 256, 0, s_side>>>(dst, E);
    k_scan1<<<nb, 1024, 0, s_side>>>(N);
    k_scan2<<<1, 256, 0, s_side>>>(nb);
    k_scan3<<<nb, 1024, 0, s_side>>>(N);
    k_scatter<<<(E + 255) / 256, 256, 0, s_side>>>(src, dst, et, enorm, E);
    cudaEventRecord(ev_join, s_side);

    // ---- main stream: node GEMMs -----------------------------------------
    k_gemm16<<<2 * sms, 512, smG>>>(ent, rel, Wn, N, R, numTilesG);
    k_gemm32<<<2 * sms, 512, smG>>>(ent, Ws, out, N, numTiles);

    // ---- join, aggregate (no smem, L1-cached relW), then gate ------------
    cudaStreamWaitEvent(0, ev_join, 0);
    k_agg2<<<(N + 7) / 8, 256>>>(out, N);
    k_final<<<2 * sms, 512, smG>>>(out, Wt, bias, his, N, numTiles);
}

// round 12
// speedup vs baseline: 2.0254x; 1.0218x over previous
#include <cuda_runtime.h>
#include <cuda_fp16.h>
#include <cstdint>
#include <math.h>

#define DHID 128
#define MAX_ENTS 100000
#define MAX_RELS 1000
#define MAX_EDGES 2000000
#define RRELU_SLOPE 0.22916666666666666f
#define PAD 132

typedef uint32_t u32;

__device__ __half2 g_hWh[MAX_ENTS * 64];         // h@Wn fp16
__device__ __half2 g_relWh[MAX_RELS * 64];       // rel@Wn fp16
__device__ int     g_cnt[MAX_ENTS];              // per-dst edge counts
__device__ int     g_off[MAX_ENTS];              // bucket start offsets
__device__ int     g_cur[MAX_ENTS];              // scatter cursors
__device__ int     g_bsum[256];                  // scan partials
__device__ uint2   g_rec[MAX_EDGES];             // (src | et<<17, norm_bits)

__device__ __forceinline__ u32 f2tf(float x) {
    u32 r; asm("cvt.rna.tf32.f32 %0, %1;" : "=r"(r) : "f"(x)); return r;
}
__device__ __forceinline__ void mma8(float* c, u32 a0, u32 a1, u32 a2, u32 a3,
                                     u32 b0, u32 b1) {
    asm volatile(
        "mma.sync.aligned.m16n8k8.row.col.f32.tf32.tf32.f32 "
        "{%0,%1,%2,%3}, {%4,%5,%6,%7}, {%8,%9}, {%0,%1,%2,%3};"
        : "+f"(c[0]), "+f"(c[1]), "+f"(c[2]), "+f"(c[3])
        : "r"(a0), "r"(a1), "r"(a2), "r"(a3), "r"(b0), "r"(b1));
}
__device__ __forceinline__ void add8(float4& acc0, float4& acc1,
                                     uint4 a, uint4 b, float n) {
    float2 p, q;
    p = __half22float2(*(__half2*)&a.x); q = __half22float2(*(__half2*)&b.x);
    acc0.x += (p.x + q.x) * n; acc0.y += (p.y + q.y) * n;
    p = __half22float2(*(__half2*)&a.y); q = __half22float2(*(__half2*)&b.y);
    acc0.z += (p.x + q.x) * n; acc0.w += (p.y + q.y) * n;
    p = __half22float2(*(__half2*)&a.z); q = __half22float2(*(__half2*)&b.z);
    acc1.x += (p.x + q.x) * n; acc1.y += (p.y + q.y) * n;
    p = __half22float2(*(__half2*)&a.w); q = __half22float2(*(__half2*)&b.w);
    acc1.z += (p.x + q.x) * n; acc1.w += (p.y + q.y) * n;
}

// ---------------------------------------------------------------------------
// Edge counting sort by dst (side stream, overlapped with GEMMs)
// ---------------------------------------------------------------------------
extern "C" __global__ void k_zero(int* __restrict__ p, int n) {
    int i = blockIdx.x * 1024 + threadIdx.x;
    if (i < n) p[i] = 0;
}

extern "C" __global__ void __launch_bounds__(256)
k_hist(const int* __restrict__ dst, int E)
{
    int e = blockIdx.x * 256 + threadIdx.x;
    if (e < E) atomicAdd(&g_cnt[dst[e]], 1);
}

extern "C" __global__ void __launch_bounds__(1024)
k_scan1(int N)
{
    __shared__ int smi[1024];
    int i = blockIdx.x * 1024 + threadIdx.x;
    int v = (i < N) ? g_cnt[i] : 0;
    smi[threadIdx.x] = v;
    __syncthreads();
    for (int off = 512; off > 0; off >>= 1) {
        if (threadIdx.x < off) smi[threadIdx.x] += smi[threadIdx.x + off];
        __syncthreads();
    }
    if (threadIdx.x == 0) g_bsum[blockIdx.x] = smi[0];
}

extern "C" __global__ void __launch_bounds__(256)
k_scan2(int nb)
{
    __shared__ int s[256];
    int t = threadIdx.x;
    int v = (t < nb) ? g_bsum[t] : 0;
    s[t] = v;
    __syncthreads();
    #pragma unroll
    for (int off = 1; off < 256; off <<= 1) {
        int x = (t >= off) ? s[t - off] : 0;
        __syncthreads();
        s[t] += x;
        __syncthreads();
    }
    if (t < nb) g_bsum[t] = s[t] - v;   // exclusive
}

extern "C" __global__ void __launch_bounds__(1024)
k_scan3(int N)
{
    __shared__ int smi[1024];
    int i = blockIdx.x * 1024 + threadIdx.x;
    int v = (i < N) ? g_cnt[i] : 0;
    smi[threadIdx.x] = v;
    __syncthreads();
    #pragma unroll
    for (int off = 1; off < 1024; off <<= 1) {
        int x = (threadIdx.x >= off) ? smi[threadIdx.x - off] : 0;
        __syncthreads();
        smi[threadIdx.x] += x;
        __syncthreads();
    }
    if (i < N) {
        int ex = smi[threadIdx.x] - v + g_bsum[blockIdx.x];
        g_off[i] = ex;
        g_cur[i] = ex;
    }
}

extern "C" __global__ void __launch_bounds__(256)
k_scatter(const int* __restrict__ src, const int* __restrict__ dst,
          const int* __restrict__ et, const float* __restrict__ enorm, int E)
{
    int e = blockIdx.x * 256 + threadIdx.x;
    if (e >= E) return;
    int d   = dst[e];
    int pos = atomicAdd(&g_cur[d], 1);
    g_rec[pos] = make_uint2((u32)src[e] | ((u32)et[e] << 17),
                            __float_as_uint(enorm[e]));
}

// ---------------------------------------------------------------------------
// k_gemm16: fp16 out = normalize(ent) @ Wn rows [0,N); rel rows [N,N+R).
// Persistent, 2 CTA/SM. smem: WT[128][PAD] | hs[64][PAD] tf32.
// ---------------------------------------------------------------------------
extern "C" __global__ void __launch_bounds__(512, 2)
k_gemm16(const float* __restrict__ ent, const float* __restrict__ rel,
         const float* __restrict__ W, int N, int R, int numTiles)
{
    extern __shared__ u32 smu[];
    u32* WT = smu;               // [n][k] tf32
    u32* hs = smu + 128 * PAD;   // [row][k] tf32
    const int tid  = threadIdx.x;
    const int lane = tid & 31;
    const int w    = tid >> 5;
    const int gid  = lane >> 2;
    const int t4   = lane & 3;

    for (int idx = tid; idx < 128 * 128; idx += 512) {
        int k = idx >> 7, n = idx & 127;
        WT[n * PAD + k] = f2tf(W[idx]);
    }
    __syncthreads();

    const int rb = (w >> 2) * 16;
    const int cb = (w & 3) * 32;

    for (int tile = blockIdx.x; tile < numTiles; tile += gridDim.x) {
        const int base = tile * 64;

        #pragma unroll
        for (int rr = 0; rr < 4; rr++) {
            int row = w * 4 + rr, node = base + row;
            uint4 o = make_uint4(0u, 0u, 0u, 0u);
            if (node < N) {
                float4 v = *(const float4*)(ent + (size_t)node * 128 + lane * 4);
                float ss = v.x * v.x + v.y * v.y + v.z * v.z + v.w * v.w;
                #pragma unroll
                for (int off = 16; off > 0; off >>= 1)
                    ss += __shfl_xor_sync(0xffffffffu, ss, off);
                float rn = 1.0f / fmaxf(sqrtf(ss), 1e-12f);
                o = make_uint4(f2tf(v.x * rn), f2tf(v.y * rn),
                               f2tf(v.z * rn), f2tf(v.w * rn));
            } else if (node < N + R) {
                float4 v = *(const float4*)(rel + (size_t)(node - N) * 128 + lane * 4);
                o = make_uint4(f2tf(v.x), f2tf(v.y), f2tf(v.z), f2tf(v.w));
            }
            *(uint4*)(hs + row * PAD + lane * 4) = o;
        }
        __syncthreads();

        float acc[4][4];
        #pragma unroll
        for (int nt = 0; nt < 4; nt++)
            #pragma unroll
            for (int i = 0; i < 4; i++) acc[nt][i] = 0.f;

        #pragma unroll
        for (int s = 0; s < 16; s++) {
            const int kb = s * 8;
            u32 a0 = hs[(rb + gid) * PAD + kb + t4];
            u32 a1 = hs[(rb + 8 + gid) * PAD + kb + t4];
            u32 a2 = hs[(rb + gid) * PAD + kb + t4 + 4];
            u32 a3 = hs[(rb + 8 + gid) * PAD + kb + t4 + 4];
            #pragma unroll
            for (int nt = 0; nt < 4; nt++) {
                int c0 = cb + nt * 8 + gid;
                u32 b0 = WT[c0 * PAD + kb + t4];
                u32 b1 = WT[c0 * PAD + kb + t4 + 4];
                mma8(acc[nt], a0, a1, a2, a3, b0, b1);
            }
        }

        #pragma unroll
        for (int nt = 0; nt < 4; nt++) {
            int rl = rb + gid;
            int c  = cb + nt * 8 + 2 * t4;
            #pragma unroll
            for (int half = 0; half < 2; half++) {
                int node = base + rl + half * 8;
                __half2 p = __floats2half2_rn(acc[nt][half * 2], acc[nt][half * 2 + 1]);
                if (node < N)          g_hWh[(size_t)node * 64 + (c >> 1)] = p;
                else if (node < N + R) g_relWh[(size_t)(node - N) * 64 + (c >> 1)] = p;
            }
        }
        __syncthreads();
    }
}

// ---------------------------------------------------------------------------
// k_gemm32: d_out = normalize(ent) @ Ws. Persistent, 2 CTA/SM.
// ---------------------------------------------------------------------------
extern "C" __global__ void __launch_bounds__(512, 2)
k_gemm32(const float* __restrict__ ent, const float* __restrict__ W,
         float* __restrict__ out, int N, int numTiles)
{
    extern __shared__ u32 smu[];
    u32* WT = smu;
    u32* hs = smu + 128 * PAD;
    const int tid  = threadIdx.x;
    const int lane = tid & 31;
    const int w    = tid >> 5;
    const int gid  = lane >> 2;
    const int t4   = lane & 3;

    for (int idx = tid; idx < 128 * 128; idx += 512) {
        int k = idx >> 7, n = idx & 127;
        WT[n * PAD + k] = f2tf(W[idx]);
    }
    __syncthreads();

    const int rb = (w >> 2) * 16;
    const int cb = (w & 3) * 32;

    for (int tile = blockIdx.x; tile < numTiles; tile += gridDim.x) {
        const int base = tile * 64;

        #pragma unroll
        for (int rr = 0; rr < 4; rr++) {
            int row = w * 4 + rr, node = base + row;
            uint4 o = make_uint4(0u, 0u, 0u, 0u);
            if (node < N) {
                float4 v = *(const float4*)(ent + (size_t)node * 128 + lane * 4);
                float ss = v.x * v.x + v.y * v.y + v.z * v.z + v.w * v.w;
                #pragma unroll
                for (int off = 16; off > 0; off >>= 1)
                    ss += __shfl_xor_sync(0xffffffffu, ss, off);
                float rn = 1.0f / fmaxf(sqrtf(ss), 1e-12f);
                o = make_uint4(f2tf(v.x * rn), f2tf(v.y * rn),
                               f2tf(v.z * rn), f2tf(v.w * rn));
            }
            *(uint4*)(hs + row * PAD + lane * 4) = o;
        }
        __syncthreads();

        float acc[4][4];
        #pragma unroll
        for (int nt = 0; nt < 4; nt++)
            #pragma unroll
            for (int i = 0; i < 4; i++) acc[nt][i] = 0.f;

        #pragma unroll
        for (int s = 0; s < 16; s++) {
            const int kb = s * 8;
            u32 a0 = hs[(rb + gid) * PAD + kb + t4];
            u32 a1 = hs[(rb + 8 + gid) * PAD + kb + t4];
            u32 a2 = hs[(rb + gid) * PAD + kb + t4 + 4];
            u32 a3 = hs[(rb + 8 + gid) * PAD + kb + t4 + 4];
            #pragma unroll
            for (int nt = 0; nt < 4; nt++) {
                int c0 = cb + nt * 8 + gid;
                u32 b0 = WT[c0 * PAD + kb + t4];
                u32 b1 = WT[c0 * PAD + kb + t4 + 4];
                mma8(acc[nt], a0, a1, a2, a3, b0, b1);
            }
        }

        #pragma unroll
        for (int nt = 0; nt < 4; nt++) {
            int rl = rb + gid;
            int c  = cb + nt * 8 + 2 * t4;
            int n0 = base + rl, n1 = base + rl + 8;
            if (n0 < N) *(float2*)(out + (size_t)n0 * 128 + c) =
                make_float2(acc[nt][0], acc[nt][1]);
            if (n1 < N) *(float2*)(out + (size_t)n1 * 128 + c) =
                make_float2(acc[nt][2], acc[nt][3]);
        }
        __syncthreads();
    }
}

// ---------------------------------------------------------------------------
// k_agg2: HALF-WARP per dst (16 lanes x uint4 = 256B row), no smem.
// acc = x[d] (h@Ws) + sum (hW[src]+relW[et])*norm; rrelu fused, in-place.
// 2 dst chains per warp x 4-edge unroll = 16 outstanding gathers/warp.
// ---------------------------------------------------------------------------
extern "C" __global__ void __launch_bounds__(256)
k_agg2(float* __restrict__ x, int N)
{
    int d = blockIdx.x * 16 + (threadIdx.x >> 4);
    if (d >= N) return;
    int l = threadIdx.x & 15;

    const uint4* hW4  = (const uint4*)g_hWh;     // 16 uint4 per row
    const uint4* rlW4 = (const uint4*)g_relWh;

    float4 acc0 = *(const float4*)(x + (size_t)d * 128 + l * 8);
    float4 acc1 = *(const float4*)(x + (size_t)d * 128 + l * 8 + 4);
    const int s0  = g_off[d];
    const int cnt = g_cnt[d];

    int i = 0;
    for (; i + 4 <= cnt; i += 4) {
        uint2 r0 = __ldg(&g_rec[s0 + i]);
        uint2 r1 = __ldg(&g_rec[s0 + i + 1]);
        uint2 r2 = __ldg(&g_rec[s0 + i + 2]);
        uint2 r3 = __ldg(&g_rec[s0 + i + 3]);
        uint4 a0 = __ldg(&hW4[(size_t)(r0.x & 0x1FFFF) * 16 + l]);
        uint4 a1 = __ldg(&hW4[(size_t)(r1.x & 0x1FFFF) * 16 + l]);
        uint4 a2 = __ldg(&hW4[(size_t)(r2.x & 0x1FFFF) * 16 + l]);
        uint4 a3 = __ldg(&hW4[(size_t)(r3.x & 0x1FFFF) * 16 + l]);
        uint4 b0 = __ldg(&rlW4[(size_t)(r0.x >> 17) * 16 + l]);
        uint4 b1 = __ldg(&rlW4[(size_t)(r1.x >> 17) * 16 + l]);
        uint4 b2 = __ldg(&rlW4[(size_t)(r2.x >> 17) * 16 + l]);
        uint4 b3 = __ldg(&rlW4[(size_t)(r3.x >> 17) * 16 + l]);
        add8(acc0, acc1, a0, b0, __uint_as_float(r0.y));
        add8(acc0, acc1, a1, b1, __uint_as_float(r1.y));
        add8(acc0, acc1, a2, b2, __uint_as_float(r2.y));
        add8(acc0, acc1, a3, b3, __uint_as_float(r3.y));
    }
    for (; i < cnt; i++) {
        uint2 r = __ldg(&g_rec[s0 + i]);
        uint4 a = __ldg(&hW4[(size_t)(r.x & 0x1FFFF) * 16 + l]);
        uint4 b = __ldg(&rlW4[(size_t)(r.x >> 17) * 16 + l]);
        add8(acc0, acc1, a, b, __uint_as_float(r.y));
    }

    acc0.x = acc0.x >= 0.f ? acc0.x : RRELU_SLOPE * acc0.x;
    acc0.y = acc0.y >= 0.f ? acc0.y : RRELU_SLOPE * acc0.y;
    acc0.z = acc0.z >= 0.f ? acc0.z : RRELU_SLOPE * acc0.z;
    acc0.w = acc0.w >= 0.f ? acc0.w : RRELU_SLOPE * acc0.w;
    acc1.x = acc1.x >= 0.f ? acc1.x : RRELU_SLOPE * acc1.x;
    acc1.y = acc1.y >= 0.f ? acc1.y : RRELU_SLOPE * acc1.y;
    acc1.z = acc1.z >= 0.f ? acc1.z : RRELU_SLOPE * acc1.z;
    acc1.w = acc1.w >= 0.f ? acc1.w : RRELU_SLOPE * acc1.w;
    *(float4*)(x + (size_t)d * 128 + l * 8)     = acc0;
    *(float4*)(x + (size_t)d * 128 + l * 8 + 4) = acc1;
}

// ---------------------------------------------------------------------------
// k_final: gate only. x holds h_cur (post-rrelu). gate = sigmoid(h_cur@Wt+b);
// x = gate*h_cur + (1-gate)*his. Persistent, 2 CTA/SM, 64-row tiles.
// ---------------------------------------------------------------------------
extern "C" __global__ void __launch_bounds__(512, 2)
k_final(float* __restrict__ x,
        const float* __restrict__ Wt,
        const float* __restrict__ bias,
        const float* __restrict__ his,
        int N, int numTiles)
{
    extern __shared__ float sm[];
    u32*   WT = (u32*)sm;          // [n][k] tf32
    float* hs = sm + 128 * PAD;    // [row][k] fp32 h_cur
    const int tid  = threadIdx.x;
    const int lane = tid & 31;
    const int w    = tid >> 5;
    const int gid  = lane >> 2;
    const int t4   = lane & 3;

    for (int idx = tid; idx < 128 * 128; idx += 512) {
        int k = idx >> 7, n = idx & 127;
        WT[n * PAD + k] = f2tf(Wt[idx]);
    }
    __syncthreads();

    const int rb = (w >> 2) * 16;
    const int cb = (w & 3) * 32;

    for (int tile = blockIdx.x; tile < numTiles; tile += gridDim.x) {
        const int base = tile * 64;

        for (int i = tid; i < 64 * 32; i += 512) {
            int row = i >> 5, kq = i & 31, node = base + row;
            float4 v = make_float4(0.f, 0.f, 0.f, 0.f);
            if (node < N) v = *(const float4*)(x + (size_t)node * 128 + kq * 4);
            *(float4*)(hs + row * PAD + kq * 4) = v;
        }
        __syncthreads();

        float acc[4][4];
        #pragma unroll
        for (int nt = 0; nt < 4; nt++)
            #pragma unroll
            for (int i = 0; i < 4; i++) acc[nt][i] = 0.f;

        #pragma unroll
        for (int s = 0; s < 16; s++) {
            const int kb = s * 8;
            u32 a0 = f2tf(hs[(rb + gid) * PAD + kb + t4]);
            u32 a1 = f2tf(hs[(rb + 8 + gid) * PAD + kb + t4]);
            u32 a2 = f2tf(hs[(rb + gid) * PAD + kb + t4 + 4]);
            u32 a3 = f2tf(hs[(rb + 8 + gid) * PAD + kb + t4 + 4]);
            #pragma unroll
            for (int nt = 0; nt < 4; nt++) {
                int c0 = cb + nt * 8 + gid;
                u32 b0 = WT[c0 * PAD + kb + t4];
                u32 b1 = WT[c0 * PAD + kb + t4 + 4];
                mma8(acc[nt], a0, a1, a2, a3, b0, b1);
            }
        }

        #pragma unroll
        for (int nt = 0; nt < 4; nt++) {
            int rl = rb + gid;
            int c  = cb + nt * 8 + 2 * t4;
            float2 bv = *(const float2*)(bias + c);
            #pragma unroll
            for (int half = 0; half < 2; half++) {
                int row  = rl + half * 8;
                int node = base + row;
                if (node >= N) continue;
                float l0 = acc[nt][half * 2 + 0] + bv.x;
                float l1 = acc[nt][half * 2 + 1] + bv.y;
                float s0 = 1.0f / (1.0f + __expf(-l0));
                float s1 = 1.0f / (1.0f + __expf(-l1));
                float2 hv = *(const float2*)(hs + row * PAD + c);
                float2 hh = *(const float2*)(his + (size_t)node * 128 + c);
                float2 o = make_float2(s0 * hv.x + (1.f - s0) * hh.x,
                                       s1 * hv.y + (1.f - s1) * hh.y);
                *(float2*)(x + (size_t)node * 128 + c) = o;
            }
        }
        __syncthreads();
    }
}

// ---------------------------------------------------------------------------
extern "C" void kernel_launch(void* const* d_in, const int* in_sizes, int n_in,
                              void* d_out, int out_size)
{
    const float* ent   = (const float*)d_in[0];
    const float* rel   = (const float*)d_in[1];
    const float* his   = (const float*)d_in[2];
    const float* Wn    = (const float*)d_in[3];
    const float* Ws    = (const float*)d_in[4];
    const float* Wt    = (const float*)d_in[5];
    const float* bias  = (const float*)d_in[6];
    const float* enorm = (const float*)d_in[7];
    const int*   src   = (const int*)d_in[8];
    const int*   dst   = (const int*)d_in[9];
    const int*   et    = (const int*)d_in[10];

    int N = in_sizes[0] / DHID;
    int R = in_sizes[1] / DHID;
    int E = in_sizes[7];
    float* out = (float*)d_out;

    int* cnt;
    cudaGetSymbolAddress((void**)&cnt, g_cnt);

    int dev = 0, sms = 148;
    cudaGetDevice(&dev);
    cudaDeviceGetAttribute(&sms, cudaDevAttrMultiProcessorCount, dev);

    const int numTiles  = (N + 63) / 64;
    const int numTilesG = (N + R + 63) / 64;
    const int nb        = (N + 1023) / 1024;
    const int smG = (128 * PAD + 64 * PAD) * sizeof(float);   // ~101.4 KB
    cudaFuncSetAttribute(k_gemm16, cudaFuncAttributeMaxDynamicSharedMemorySize, smG);
    cudaFuncSetAttribute(k_gemm32, cudaFuncAttributeMaxDynamicSharedMemorySize, smG);
    cudaFuncSetAttribute(k_final,  cudaFuncAttributeMaxDynamicSharedMemorySize, smG);
    cudaFuncSetAttribute(k_agg2, cudaFuncAttributePreferredSharedMemoryCarveout,
                         cudaSharedmemCarveoutMaxL1);

    static cudaStream_t s_side = nullptr;
    static cudaEvent_t  ev_fork = nullptr, ev_join = nullptr;
    if (s_side == nullptr) {
        cudaStreamCreateWithFlags(&s_side, cudaStreamNonBlocking);
        cudaEventCreateWithFlags(&ev_fork, cudaEventDisableTiming);
        cudaEventCreateWithFlags(&ev_join, cudaEventDisableTiming);
    }

    // ---- fork: edge counting-sort chain on side stream -------------------
    cudaEventRecord(ev_fork, 0);
    cudaStreamWaitEvent(s_side, ev_fork, 0);
    k_zero<<<nb, 1024, 0, s_side>>>(cnt, N);
    k_hist<<<(E + 255) / 256, 256, 0, s_side>>>(dst, E);
    k_scan1<<<nb, 1024, 0, s_side>>>(N);
    k_scan2<<<1, 256, 0, s_side>>>(nb);
    k_scan3<<<nb, 1024, 0, s_side>>>(N);
    k_scatter<<<(E + 255) / 256, 256, 0, s_side>>>(src, dst, et, enorm, E);
    cudaEventRecord(ev_join, s_side);

    // ---- main stream: node GEMMs -----------------------------------------
    k_gemm16<<<2 * sms, 512, smG>>>(ent, rel, Wn, N, R, numTilesG);
    k_gemm32<<<2 * sms, 512, smG>>>(ent, Ws, out, N, numTiles);

    // ---- join, aggregate (half-warp per dst), then gate ------------------
    cudaStreamWaitEvent(0, ev_join, 0);
    k_agg2<<<(N + 15) / 16, 256>>>(out, N);
    k_final<<<2 * sms, 512, smG>>>(out, Wt, bias, his, N, numTiles);
}